// round 1
// baseline (speedup 1.0000x reference)
#include <cuda_runtime.h>
#include <math.h>

// Problem constants
#define B     64
#define S     128
#define E     512
#define H     512
#define A_DIM 256
#define V     8192
#define T     32
#define KX    1024   // H + E (LSTM input x = [emb, ctx])
#define KG    1536   // H + E + H (fused gates input [x, h])
#define G4    2048   // 4*H

// -------------------- scratch (device globals; no allocs allowed) ----------
__device__ float g_encproj[B * S * A_DIM];   // 8.4 MB
__device__ float g_WencT[A_DIM * E];         // W_enc transposed: [A, E]
__device__ float g_Wf[G4 * KG];              // fused [W_ih | W_hh], 12.6 MB
__device__ float g_bf[G4];                   // b_ih + b_hh
__device__ float g_xh[B * KG];               // [emb | ctx | h_prev]
__device__ float g_hcat[B * KX];             // [h_new | ctx]
__device__ float g_c[B * H];                 // LSTM cell state
__device__ float g_gates[B * G4];            // gates pre-activation

// -------------------- setup: transpose W_enc, fuse W_ih/W_hh, zero state ---
__global__ void k_prep(const float* __restrict__ W_enc,
                       const float* __restrict__ W_ih,
                       const float* __restrict__ W_hh,
                       const float* __restrict__ b_ih,
                       const float* __restrict__ b_hh) {
    int stride = gridDim.x * blockDim.x;
    int tid0 = blockIdx.x * blockDim.x + threadIdx.x;
    for (int i = tid0; i < A_DIM * E; i += stride) {
        int a = i / E, e = i % E;
        g_WencT[i] = W_enc[e * A_DIM + a];
    }
    for (int i = tid0; i < G4 * KG; i += stride) {
        int j = i / KG, k = i % KG;
        g_Wf[i] = (k < KX) ? W_ih[j * KX + k] : W_hh[j * H + (k - KX)];
    }
    for (int i = tid0; i < G4; i += stride) g_bf[i] = b_ih[i] + b_hh[i];
    for (int i = tid0; i < B * H; i += stride) {
        g_c[i] = 0.0f;
        int b = i / H, j = i % H;
        g_xh[b * KG + KX + j] = 0.0f;   // h0 = 0
    }
}

// -------------------- generic tiled fp32 GEMM: C = A * B^T (+bias) ---------
// A: [M,K] row-major (lda = K); Bm: [N,K] row-major (ldb = K);
// C: row stride ldc. All of M,N % 64 == 0 and K % 16 == 0 by construction.
#define BM 64
#define BN 64
#define BK 16
__global__ __launch_bounds__(256)
void k_gemm(const float* __restrict__ Am, const float* __restrict__ Bm,
            const float* __restrict__ bias, float* __restrict__ C,
            int M, int N, int K, int ldc) {
    __shared__ __align__(16) float As[BK][BM];
    __shared__ __align__(16) float Bs[BK][BN];
    int tx = threadIdx.x, ty = threadIdx.y;       // 16 x 16
    int tid = ty * 16 + tx;
    int m0 = blockIdx.y * BM, n0 = blockIdx.x * BN;

    float acc[4][4] = {};

    for (int k0 = 0; k0 < K; k0 += BK) {
        #pragma unroll
        for (int i = 0; i < 4; i++) {
            int idx = tid + i * 256;              // 0..1023
            int r = idx >> 4, kk = idx & 15;
            As[kk][r] = Am[(m0 + r) * K + k0 + kk];
            Bs[kk][r] = Bm[(n0 + r) * K + k0 + kk];
        }
        __syncthreads();
        #pragma unroll
        for (int kk = 0; kk < BK; kk++) {
            float4 a4 = *(const float4*)&As[kk][ty * 4];
            float4 b4 = *(const float4*)&Bs[kk][tx * 4];
            float a[4] = {a4.x, a4.y, a4.z, a4.w};
            float b[4] = {b4.x, b4.y, b4.z, b4.w};
            #pragma unroll
            for (int i = 0; i < 4; i++)
                #pragma unroll
                for (int j = 0; j < 4; j++)
                    acc[i][j] += a[i] * b[j];
        }
        __syncthreads();
    }

    float4 bb = make_float4(0.f, 0.f, 0.f, 0.f);
    if (bias) bb = *(const float4*)&bias[n0 + tx * 4];
    #pragma unroll
    for (int i = 0; i < 4; i++) {
        float4 v;
        v.x = acc[i][0] + bb.x;
        v.y = acc[i][1] + bb.y;
        v.z = acc[i][2] + bb.z;
        v.w = acc[i][3] + bb.w;
        *(float4*)&C[(size_t)(m0 + ty * 4 + i) * ldc + n0 + tx * 4] = v;
    }
}

// -------------------- attention (one block per batch element) --------------
__global__ __launch_bounds__(256)
void k_attn(const float* __restrict__ enc, const int* __restrict__ tgt,
            const float* __restrict__ emb, const float* __restrict__ W_dec,
            const float* __restrict__ b_att, const float* __restrict__ v_att,
            int t) {
    int b = blockIdx.x;
    int tid = threadIdx.x;          // 256 threads
    __shared__ float sh_h[H];
    __shared__ float sh_dp[A_DIM];
    __shared__ float sh_v[A_DIM];
    __shared__ float sh_sc[S];

    // load previous hidden state + v_att
    sh_h[tid]       = g_xh[b * KG + KX + tid];
    sh_h[tid + 256] = g_xh[b * KG + KX + tid + 256];
    sh_v[tid < A_DIM ? tid : 0] = v_att[tid < A_DIM ? tid : 0];
    __syncthreads();

    // dp[a] = b_att[a] + h . W_dec[:,a]
    {
        float acc = b_att[tid];
        #pragma unroll 4
        for (int e = 0; e < H; e++) acc += sh_h[e] * W_dec[e * A_DIM + tid];
        sh_dp[tid] = acc;
    }
    __syncthreads();

    // scores[s] = sum_a tanh(encproj[b,s,a] + dp[a]) * v[a]
    int warp = tid >> 5, lane = tid & 31;
    for (int s = warp; s < S; s += 8) {
        const float* ep = &g_encproj[((size_t)b * S + s) * A_DIM];
        float acc = 0.f;
        #pragma unroll
        for (int a = lane; a < A_DIM; a += 32)
            acc += tanhf(ep[a] + sh_dp[a]) * sh_v[a];
        #pragma unroll
        for (int o = 16; o; o >>= 1) acc += __shfl_xor_sync(0xffffffffu, acc, o);
        if (lane == 0) sh_sc[s] = acc;
    }
    __syncthreads();

    // softmax over S=128 (warp 0)
    if (warp == 0) {
        float v0 = sh_sc[lane], v1 = sh_sc[lane + 32];
        float v2 = sh_sc[lane + 64], v3 = sh_sc[lane + 96];
        float m = fmaxf(fmaxf(v0, v1), fmaxf(v2, v3));
        #pragma unroll
        for (int o = 16; o; o >>= 1) m = fmaxf(m, __shfl_xor_sync(0xffffffffu, m, o));
        float e0 = expf(v0 - m), e1 = expf(v1 - m);
        float e2 = expf(v2 - m), e3 = expf(v3 - m);
        float sum = e0 + e1 + e2 + e3;
        #pragma unroll
        for (int o = 16; o; o >>= 1) sum += __shfl_xor_sync(0xffffffffu, sum, o);
        float inv = 1.f / sum;
        sh_sc[lane] = e0 * inv;        sh_sc[lane + 32] = e1 * inv;
        sh_sc[lane + 64] = e2 * inv;   sh_sc[lane + 96] = e3 * inv;
    }
    __syncthreads();

    // ctx[e] = sum_s w[s] * enc[b,s,e]
    for (int e = tid; e < E; e += 256) {
        float acc = 0.f;
        const float* eb = &enc[((size_t)b * S) * E + e];
        #pragma unroll 8
        for (int s = 0; s < S; s++) acc += sh_sc[s] * eb[(size_t)s * E];
        g_xh[b * KG + H + e]   = acc;   // x = [emb | ctx]
        g_hcat[b * KX + H + e] = acc;   // out input = [h_new | ctx]
    }

    // x_emb (teacher forcing: token 0 at t=0, else target[:, t-1])
    int tok = (t == 0) ? 0 : tgt[b * T + t - 1];
    for (int j = tid; j < H; j += 256)
        g_xh[b * KG + j] = emb[(size_t)tok * H + j];
}

// -------------------- LSTM elementwise update ------------------------------
__global__ __launch_bounds__(256)
void k_lstm() {
    int idx = blockIdx.x * blockDim.x + threadIdx.x;  // B*H = 32768
    if (idx >= B * H) return;
    int b = idx / H, j = idx % H;
    const float* g = &g_gates[b * G4];
    float gi = g[j], gf = g[j + H], gg = g[j + 2 * H], go = g[j + 3 * H];
    float c = g_c[idx];
    float si = 1.f / (1.f + expf(-gi));
    float sf = 1.f / (1.f + expf(-gf));
    float so = 1.f / (1.f + expf(-go));
    float cn = sf * c + si * tanhf(gg);
    float hn = so * tanhf(cn);
    g_c[idx] = cn;
    g_xh[b * KG + KX + j] = hn;   // h for next step's attention/gates
    g_hcat[b * KX + j]    = hn;   // h for this step's output projection
}

// -------------------- launch ----------------------------------------------
extern "C" void kernel_launch(void* const* d_in, const int* in_sizes, int n_in,
                              void* d_out, int out_size) {
    const float* enc   = (const float*)d_in[0];
    const int*   tgt   = (const int*)  d_in[1];
    const float* emb   = (const float*)d_in[2];
    const float* W_enc = (const float*)d_in[3];
    const float* W_dec = (const float*)d_in[4];
    const float* b_att = (const float*)d_in[5];
    const float* v_att = (const float*)d_in[6];
    const float* W_ih  = (const float*)d_in[7];
    const float* W_hh  = (const float*)d_in[8];
    const float* b_ih  = (const float*)d_in[9];
    const float* b_hh  = (const float*)d_in[10];
    const float* W_out = (const float*)d_in[11];
    const float* b_out = (const float*)d_in[12];
    float* out = (float*)d_out;

    float *p_encproj, *p_WencT, *p_Wf, *p_bf, *p_xh, *p_hcat, *p_gates;
    cudaGetSymbolAddress((void**)&p_encproj, g_encproj);
    cudaGetSymbolAddress((void**)&p_WencT,   g_WencT);
    cudaGetSymbolAddress((void**)&p_Wf,      g_Wf);
    cudaGetSymbolAddress((void**)&p_bf,      g_bf);
    cudaGetSymbolAddress((void**)&p_xh,      g_xh);
    cudaGetSymbolAddress((void**)&p_hcat,    g_hcat);
    cudaGetSymbolAddress((void**)&p_gates,   g_gates);

    dim3 blk(16, 16);

    // setup: transpose + fuse + zero state
    k_prep<<<512, 256>>>(W_enc, W_ih, W_hh, b_ih, b_hh);

    // enc_proj = enc[B*S, E] @ W_enc  -> use WencT as [A, E] (C = A * B^T)
    {
        dim3 grid(A_DIM / BN, (B * S) / BM);   // (4, 128)
        k_gemm<<<grid, blk>>>(enc, p_WencT, nullptr, p_encproj,
                              B * S, A_DIM, E, A_DIM);
    }

    for (int t = 0; t < T; t++) {
        // attention + embed gather -> g_xh, g_hcat[ctx]
        k_attn<<<B, 256>>>(enc, tgt, emb, W_dec, b_att, v_att, t);

        // gates = [x, h] @ Wf^T + bf   (M=64, N=2048, K=1536)
        {
            dim3 grid(G4 / BN, B / BM);        // (32, 1)
            k_gemm<<<grid, blk>>>(p_xh, p_Wf, p_bf, p_gates,
                                  B, G4, KG, G4);
        }

        // LSTM update -> h_new (g_xh h-slot, g_hcat), c
        k_lstm<<<(B * H + 255) / 256, 256>>>();

        // out[:, t, :] = [h_new, ctx] @ W_out^T + b_out  (M=64, N=8192, K=1024)
        {
            dim3 grid(V / BN, B / BM);         // (128, 1)
            k_gemm<<<grid, blk>>>(p_hcat, W_out, b_out, out + (size_t)t * V,
                                  B, V, KX, (int)T * V);
        }
    }
}

// round 2
// speedup vs baseline: 2.1372x; 2.1372x over previous
#include <cuda_runtime.h>
#include <math.h>

// Problem constants
#define B     64
#define S     128
#define E     512
#define H     512
#define A_DIM 256
#define V     8192
#define T     32
#define KX    1024   // H + E
#define KG    1536   // H + E + H
#define G4    2048   // 4*H
#define KSPLIT 8
#define KCHUNK (KG / KSPLIT)   // 192

// -------------------- scratch (device globals) -----------------------------
__device__ float g_encproj[B * S * A_DIM];    // 8.4 MB
__device__ float g_WencT[A_DIM * E];
__device__ float g_Wf[G4 * KG];               // fused [W_ih | W_hh]
__device__ float g_bf[G4];
__device__ float g_xh[B * KG];                // [emb | ctx | h_prev]
__device__ float g_hcatall[T * B * KX];       // [h_t | ctx_t] for all steps (8 MB)
__device__ float g_c[B * H];
__device__ float g_gpart[KSPLIT * B * G4];    // split-K partial gates (4 MB)

// -------------------- setup -------------------------------------------------
__global__ void k_prep(const float* __restrict__ W_enc,
                       const float* __restrict__ W_ih,
                       const float* __restrict__ W_hh,
                       const float* __restrict__ b_ih,
                       const float* __restrict__ b_hh) {
    int stride = gridDim.x * blockDim.x;
    int tid0 = blockIdx.x * blockDim.x + threadIdx.x;
    for (int i = tid0; i < A_DIM * E; i += stride) {
        int a = i / E, e = i % E;
        g_WencT[i] = W_enc[e * A_DIM + a];
    }
    for (int i = tid0; i < G4 * KG; i += stride) {
        int j = i / KG, k = i % KG;
        g_Wf[i] = (k < KX) ? W_ih[j * KX + k] : W_hh[j * H + (k - KX)];
    }
    for (int i = tid0; i < G4; i += stride) g_bf[i] = b_ih[i] + b_hh[i];
    for (int i = tid0; i < B * H; i += stride) {
        g_c[i] = 0.0f;
        int b = i / H, j = i % H;
        g_xh[b * KG + KX + j] = 0.0f;   // h0 = 0
    }
}

// -------------------- generic tiled fp32 GEMM (enc_proj only) --------------
#define BM 64
#define BN 64
#define BK 16
__global__ __launch_bounds__(256)
void k_gemm(const float* __restrict__ Am, const float* __restrict__ Bm,
            float* __restrict__ C, int M, int N, int K, int ldc) {
    __shared__ __align__(16) float As[BK][BM];
    __shared__ __align__(16) float Bs[BK][BN];
    int tx = threadIdx.x & 15, ty = threadIdx.x >> 4;
    int tid = threadIdx.x;
    int m0 = blockIdx.y * BM, n0 = blockIdx.x * BN;
    float acc[4][4] = {};
    for (int k0 = 0; k0 < K; k0 += BK) {
        #pragma unroll
        for (int i = 0; i < 4; i++) {
            int idx = tid + i * 256;
            int r = idx >> 4, kk = idx & 15;
            As[kk][r] = Am[(size_t)(m0 + r) * K + k0 + kk];
            Bs[kk][r] = Bm[(size_t)(n0 + r) * K + k0 + kk];
        }
        __syncthreads();
        #pragma unroll
        for (int kk = 0; kk < BK; kk++) {
            float4 a4 = *(const float4*)&As[kk][ty * 4];
            float4 b4 = *(const float4*)&Bs[kk][tx * 4];
            float a[4] = {a4.x, a4.y, a4.z, a4.w};
            float b[4] = {b4.x, b4.y, b4.z, b4.w};
            #pragma unroll
            for (int i = 0; i < 4; i++)
                #pragma unroll
                for (int j = 0; j < 4; j++)
                    acc[i][j] += a[i] * b[j];
        }
        __syncthreads();
    }
    #pragma unroll
    for (int i = 0; i < 4; i++) {
        float4 v = {acc[i][0], acc[i][1], acc[i][2], acc[i][3]};
        *(float4*)&C[(size_t)(m0 + ty * 4 + i) * ldc + n0 + tx * 4] = v;
    }
}

// -------------------- gates GEMM, split-K=8 --------------------------------
// partial[kc] = g_xh[64, chunk] @ g_Wf[2048, chunk]^T
__global__ __launch_bounds__(256)
void k_gates() {
    __shared__ __align__(16) float As[BK][BM];
    __shared__ __align__(16) float Bs[BK][BN];
    int tx = threadIdx.x & 15, ty = threadIdx.x >> 4;
    int tid = threadIdx.x;
    int n0 = blockIdx.x * BN;
    int kc = blockIdx.y;
    int kbase = kc * KCHUNK;
    float acc[4][4] = {};
    for (int k0 = kbase; k0 < kbase + KCHUNK; k0 += BK) {
        #pragma unroll
        for (int i = 0; i < 4; i++) {
            int idx = tid + i * 256;
            int r = idx >> 4, kk = idx & 15;
            As[kk][r] = g_xh[r * KG + k0 + kk];
            Bs[kk][r] = g_Wf[(size_t)(n0 + r) * KG + k0 + kk];
        }
        __syncthreads();
        #pragma unroll
        for (int kk = 0; kk < BK; kk++) {
            float4 a4 = *(const float4*)&As[kk][ty * 4];
            float4 b4 = *(const float4*)&Bs[kk][tx * 4];
            float a[4] = {a4.x, a4.y, a4.z, a4.w};
            float b[4] = {b4.x, b4.y, b4.z, b4.w};
            #pragma unroll
            for (int i = 0; i < 4; i++)
                #pragma unroll
                for (int j = 0; j < 4; j++)
                    acc[i][j] += a[i] * b[j];
        }
        __syncthreads();
    }
    #pragma unroll
    for (int i = 0; i < 4; i++) {
        float4 v = {acc[i][0], acc[i][1], acc[i][2], acc[i][3]};
        *(float4*)&g_gpart[(size_t)(kc * B + ty * 4 + i) * G4 + n0 + tx * 4] = v;
    }
}

// -------------------- fused LSTM(t-1) + attention(t) ------------------------
// t in [0, T]: if t>0 apply LSTM from g_gpart; if t<T run attention for step t.
__global__ __launch_bounds__(256)
void k_step(const float* __restrict__ enc, const int* __restrict__ tgt,
            const float* __restrict__ emb, const float* __restrict__ W_dec,
            const float* __restrict__ b_att, const float* __restrict__ v_att,
            int t) {
    int b = blockIdx.x;
    int tid = threadIdx.x;
    __shared__ float sh_h[H];
    __shared__ float sh_dp[A_DIM];
    __shared__ float sh_v[A_DIM];
    __shared__ float sh_sc[S];

    // ---- LSTM elementwise for step t-1 ----
    if (t > 0) {
        #pragma unroll
        for (int jj = 0; jj < 2; jj++) {
            int j = tid + jj * 256;
            float gi = g_bf[j], gf = g_bf[j + H];
            float gg = g_bf[j + 2 * H], go = g_bf[j + 3 * H];
            #pragma unroll
            for (int p = 0; p < KSPLIT; p++) {
                const float* gp = &g_gpart[(size_t)(p * B + b) * G4];
                gi += gp[j];         gf += gp[j + H];
                gg += gp[j + 2 * H]; go += gp[j + 3 * H];
            }
            float c = g_c[b * H + j];
            float si = 1.f / (1.f + expf(-gi));
            float sf = 1.f / (1.f + expf(-gf));
            float so = 1.f / (1.f + expf(-go));
            float cn = sf * c + si * tanhf(gg);
            float hn = so * tanhf(cn);
            g_c[b * H + j] = cn;
            sh_h[j] = hn;
            g_xh[b * KG + KX + j] = hn;
            g_hcatall[(size_t)((t - 1) * B + b) * KX + j] = hn;
        }
    } else {
        sh_h[tid] = 0.f;
        sh_h[tid + 256] = 0.f;
    }
    if (t >= T) return;   // t==T: only the final LSTM was needed
    sh_v[tid] = v_att[tid];
    __syncthreads();

    // dp[a] = b_att[a] + h . W_dec[:,a]
    {
        float acc = b_att[tid];
        #pragma unroll 4
        for (int e = 0; e < H; e++) acc += sh_h[e] * W_dec[e * A_DIM + tid];
        sh_dp[tid] = acc;
    }
    __syncthreads();

    // scores
    int warp = tid >> 5, lane = tid & 31;
    for (int s = warp; s < S; s += 8) {
        const float* ep = &g_encproj[((size_t)b * S + s) * A_DIM];
        float acc = 0.f;
        #pragma unroll
        for (int a = lane; a < A_DIM; a += 32)
            acc += tanhf(ep[a] + sh_dp[a]) * sh_v[a];
        #pragma unroll
        for (int o = 16; o; o >>= 1) acc += __shfl_xor_sync(0xffffffffu, acc, o);
        if (lane == 0) sh_sc[s] = acc;
    }
    __syncthreads();

    // softmax over S=128
    if (warp == 0) {
        float v0 = sh_sc[lane], v1 = sh_sc[lane + 32];
        float v2 = sh_sc[lane + 64], v3 = sh_sc[lane + 96];
        float m = fmaxf(fmaxf(v0, v1), fmaxf(v2, v3));
        #pragma unroll
        for (int o = 16; o; o >>= 1) m = fmaxf(m, __shfl_xor_sync(0xffffffffu, m, o));
        float e0 = expf(v0 - m), e1 = expf(v1 - m);
        float e2 = expf(v2 - m), e3 = expf(v3 - m);
        float sum = e0 + e1 + e2 + e3;
        #pragma unroll
        for (int o = 16; o; o >>= 1) sum += __shfl_xor_sync(0xffffffffu, sum, o);
        float inv = 1.f / sum;
        sh_sc[lane] = e0 * inv;        sh_sc[lane + 32] = e1 * inv;
        sh_sc[lane + 64] = e2 * inv;   sh_sc[lane + 96] = e3 * inv;
    }
    __syncthreads();

    // ctx
    for (int e = tid; e < E; e += 256) {
        float acc = 0.f;
        const float* eb = &enc[((size_t)b * S) * E + e];
        #pragma unroll 8
        for (int s = 0; s < S; s++) acc += sh_sc[s] * eb[(size_t)s * E];
        g_xh[b * KG + H + e] = acc;
        g_hcatall[(size_t)(t * B + b) * KX + H + e] = acc;
    }

    // x_emb
    int tok = (t == 0) ? 0 : tgt[b * T + t - 1];
    for (int j = tid; j < H; j += 256)
        g_xh[b * KG + j] = emb[(size_t)tok * H + j];
}

// -------------------- big output GEMM: [T*B, V] = hcat @ W_out^T + b --------
#define OBM 128
#define OBN 128
#define OBK 8
#define OPAD 4
__global__ __launch_bounds__(256, 2)
void k_out_gemm(const float* __restrict__ Bw, const float* __restrict__ bias,
                float* __restrict__ out) {
    __shared__ __align__(16) float As[OBK][OBM + OPAD];
    __shared__ __align__(16) float Bs[OBK][OBN + OPAD];
    int tid = threadIdx.x;
    int tx = tid & 15, ty = tid >> 4;
    int m0 = blockIdx.y * OBM, n0 = blockIdx.x * OBN;
    int lr = tid >> 1;
    int lk = (tid & 1) * 4;
    const float* Aptr = &g_hcatall[(size_t)(m0 + lr) * KX + lk];
    const float* Bptr = Bw + (size_t)(n0 + lr) * KX + lk;
    float acc[8][8] = {};
    for (int k0 = 0; k0 < KX; k0 += OBK) {
        float4 av = *(const float4*)(Aptr + k0);
        float4 bv = *(const float4*)(Bptr + k0);
        As[lk + 0][lr] = av.x; As[lk + 1][lr] = av.y;
        As[lk + 2][lr] = av.z; As[lk + 3][lr] = av.w;
        Bs[lk + 0][lr] = bv.x; Bs[lk + 1][lr] = bv.y;
        Bs[lk + 2][lr] = bv.z; Bs[lk + 3][lr] = bv.w;
        __syncthreads();
        #pragma unroll
        for (int k = 0; k < OBK; k++) {
            float4 a0 = *(const float4*)&As[k][ty * 8];
            float4 a1 = *(const float4*)&As[k][ty * 8 + 4];
            float4 b0 = *(const float4*)&Bs[k][tx * 8];
            float4 b1 = *(const float4*)&Bs[k][tx * 8 + 4];
            float a[8] = {a0.x, a0.y, a0.z, a0.w, a1.x, a1.y, a1.z, a1.w};
            float bb[8] = {b0.x, b0.y, b0.z, b0.w, b1.x, b1.y, b1.z, b1.w};
            #pragma unroll
            for (int i = 0; i < 8; i++)
                #pragma unroll
                for (int j = 0; j < 8; j++)
                    acc[i][j] += a[i] * bb[j];
        }
        __syncthreads();
    }
    float4 bb0 = *(const float4*)&bias[n0 + tx * 8];
    float4 bb1 = *(const float4*)&bias[n0 + tx * 8 + 4];
    float bv[8] = {bb0.x, bb0.y, bb0.z, bb0.w, bb1.x, bb1.y, bb1.z, bb1.w};
    #pragma unroll
    for (int i = 0; i < 8; i++) {
        int r = m0 + ty * 8 + i;
        int bidx = r & (B - 1);      // r = t*B + b
        int tt = r >> 6;
        float* orow = out + (size_t)bidx * T * V + (size_t)tt * V + n0 + tx * 8;
        float4 v0 = {acc[i][0] + bv[0], acc[i][1] + bv[1],
                     acc[i][2] + bv[2], acc[i][3] + bv[3]};
        float4 v1 = {acc[i][4] + bv[4], acc[i][5] + bv[5],
                     acc[i][6] + bv[6], acc[i][7] + bv[7]};
        *(float4*)orow = v0;
        *(float4*)(orow + 4) = v1;
    }
}

// -------------------- launch ------------------------------------------------
extern "C" void kernel_launch(void* const* d_in, const int* in_sizes, int n_in,
                              void* d_out, int out_size) {
    const float* enc   = (const float*)d_in[0];
    const int*   tgt   = (const int*)  d_in[1];
    const float* emb   = (const float*)d_in[2];
    const float* W_enc = (const float*)d_in[3];
    const float* W_dec = (const float*)d_in[4];
    const float* b_att = (const float*)d_in[5];
    const float* v_att = (const float*)d_in[6];
    const float* W_ih  = (const float*)d_in[7];
    const float* W_hh  = (const float*)d_in[8];
    const float* b_ih  = (const float*)d_in[9];
    const float* b_hh  = (const float*)d_in[10];
    const float* W_out = (const float*)d_in[11];
    const float* b_out = (const float*)d_in[12];
    float* out = (float*)d_out;

    float *p_encproj, *p_WencT;
    cudaGetSymbolAddress((void**)&p_encproj, g_encproj);
    cudaGetSymbolAddress((void**)&p_WencT,   g_WencT);

    k_prep<<<512, 256>>>(W_enc, W_ih, W_hh, b_ih, b_hh);

    // enc_proj = enc[B*S, E] @ W_enc -> [B*S, A]
    {
        dim3 grid(A_DIM / BN, (B * S) / BM);
        k_gemm<<<grid, 256>>>(enc, p_WencT, p_encproj, B * S, A_DIM, E, A_DIM);
    }

    for (int t = 0; t < T; t++) {
        k_step<<<B, 256>>>(enc, tgt, emb, W_dec, b_att, v_att, t);
        dim3 grid(G4 / BN, KSPLIT);
        k_gates<<<grid, 256>>>();
    }
    // final LSTM (produces h_{T-1} into g_hcatall)
    k_step<<<B, 256>>>(enc, tgt, emb, W_dec, b_att, v_att, T);

    // one big output projection for all timesteps
    {
        dim3 grid(V / OBN, (T * B) / OBM);
        k_out_gemm<<<grid, 256>>>(W_out, b_out, out);
    }
}

// round 3
// speedup vs baseline: 3.2643x; 1.5274x over previous
#include <cuda_runtime.h>
#include <math.h>

// Problem constants
#define B     64
#define S     128
#define E     512
#define H     512
#define A_DIM 256
#define V     8192
#define T     32
#define KX    1024   // H + E
#define KG    1536   // H + E + H
#define G4    2048   // 4*H
#define KSPLIT 16
#define KCHUNK (KG / KSPLIT)   // 96

// -------------------- scratch (device globals) -----------------------------
__device__ float g_encproj[B * S * A_DIM];    // 8.4 MB
__device__ float g_WencT[A_DIM * E];
__device__ float g_Wf[G4 * KG];               // fused [W_ih | W_hh]
__device__ float g_bf[G4];
__device__ float g_xh[B * KG];                // [emb | ctx | h_prev]
__device__ float g_hcatall[T * B * KX];       // [h_t | ctx_t] for all steps
__device__ float g_c[B * H];
__device__ float g_gpart[KSPLIT * B * G4];    // split-K partial gates (8 MB)

// -------------------- helpers ----------------------------------------------
__device__ __forceinline__ unsigned f2tf32(float x) {
    unsigned r;
    asm("cvt.rna.tf32.f32 %0, %1;" : "=r"(r) : "f"(x));
    return r;
}
__device__ __forceinline__ float tanh_fast(float x) {
    float y;
    asm("tanh.approx.f32 %0, %1;" : "=f"(y) : "f"(x));
    return y;
}
__device__ __forceinline__ void mma_tf32(float* d, const unsigned* a, const unsigned* b) {
    asm("mma.sync.aligned.m16n8k8.row.col.f32.tf32.tf32.f32 "
        "{%0,%1,%2,%3}, {%4,%5,%6,%7}, {%8,%9}, {%0,%1,%2,%3};"
        : "+f"(d[0]), "+f"(d[1]), "+f"(d[2]), "+f"(d[3])
        : "r"(a[0]), "r"(a[1]), "r"(a[2]), "r"(a[3]), "r"(b[0]), "r"(b[1]));
}

// -------------------- setup -------------------------------------------------
__global__ void k_prep(const float* __restrict__ W_enc,
                       const float* __restrict__ W_ih,
                       const float* __restrict__ W_hh,
                       const float* __restrict__ b_ih,
                       const float* __restrict__ b_hh) {
    int stride = gridDim.x * blockDim.x;
    int tid0 = blockIdx.x * blockDim.x + threadIdx.x;
    for (int i = tid0; i < A_DIM * E; i += stride) {
        int a = i / E, e = i % E;
        g_WencT[i] = W_enc[e * A_DIM + a];
    }
    for (int i = tid0; i < G4 * KG; i += stride) {
        int j = i / KG, k = i % KG;
        g_Wf[i] = (k < KX) ? W_ih[j * KX + k] : W_hh[j * H + (k - KX)];
    }
    for (int i = tid0; i < G4; i += stride) g_bf[i] = b_ih[i] + b_hh[i];
    for (int i = tid0; i < B * H; i += stride) {
        g_c[i] = 0.0f;
        int b = i / H, j = i % H;
        g_xh[b * KG + KX + j] = 0.0f;   // h0 = 0
    }
}

// -------------------- generic tiled fp32 GEMM (enc_proj) -------------------
#define BM 64
#define BN 64
#define BK 16
__global__ __launch_bounds__(256)
void k_gemm(const float* __restrict__ Am, const float* __restrict__ Bm,
            float* __restrict__ C, int M, int N, int K, int ldc) {
    __shared__ __align__(16) float As[BK][BM];
    __shared__ __align__(16) float Bs[BK][BN];
    int tx = threadIdx.x & 15, ty = threadIdx.x >> 4;
    int tid = threadIdx.x;
    int m0 = blockIdx.y * BM, n0 = blockIdx.x * BN;
    float acc[4][4] = {};
    for (int k0 = 0; k0 < K; k0 += BK) {
        #pragma unroll
        for (int i = 0; i < 4; i++) {
            int idx = tid + i * 256;
            int r = idx >> 4, kk = idx & 15;
            As[kk][r] = Am[(size_t)(m0 + r) * K + k0 + kk];
            Bs[kk][r] = Bm[(size_t)(n0 + r) * K + k0 + kk];
        }
        __syncthreads();
        #pragma unroll
        for (int kk = 0; kk < BK; kk++) {
            float4 a4 = *(const float4*)&As[kk][ty * 4];
            float4 b4 = *(const float4*)&Bs[kk][tx * 4];
            float a[4] = {a4.x, a4.y, a4.z, a4.w};
            float b[4] = {b4.x, b4.y, b4.z, b4.w};
            #pragma unroll
            for (int i = 0; i < 4; i++)
                #pragma unroll
                for (int j = 0; j < 4; j++)
                    acc[i][j] += a[i] * b[j];
        }
        __syncthreads();
    }
    #pragma unroll
    for (int i = 0; i < 4; i++) {
        float4 v = {acc[i][0], acc[i][1], acc[i][2], acc[i][3]};
        *(float4*)&C[(size_t)(m0 + ty * 4 + i) * ldc + n0 + tx * 4] = v;
    }
}

// -------------------- gates GEMM, split-K=16 -------------------------------
__global__ __launch_bounds__(256)
void k_gates() {
    __shared__ __align__(16) float As[BK][BM];
    __shared__ __align__(16) float Bs[BK][BN];
    int tx = threadIdx.x & 15, ty = threadIdx.x >> 4;
    int tid = threadIdx.x;
    int n0 = blockIdx.x * BN;
    int kc = blockIdx.y;
    int kbase = kc * KCHUNK;
    float acc[4][4] = {};
    #pragma unroll
    for (int kb = 0; kb < KCHUNK; kb += BK) {
        int k0 = kbase + kb;
        #pragma unroll
        for (int i = 0; i < 4; i++) {
            int idx = tid + i * 256;
            int r = idx >> 4, kk = idx & 15;
            As[kk][r] = g_xh[r * KG + k0 + kk];
            Bs[kk][r] = g_Wf[(size_t)(n0 + r) * KG + k0 + kk];
        }
        __syncthreads();
        #pragma unroll
        for (int kk = 0; kk < BK; kk++) {
            float4 a4 = *(const float4*)&As[kk][ty * 4];
            float4 b4 = *(const float4*)&Bs[kk][tx * 4];
            float a[4] = {a4.x, a4.y, a4.z, a4.w};
            float b[4] = {b4.x, b4.y, b4.z, b4.w};
            #pragma unroll
            for (int i = 0; i < 4; i++)
                #pragma unroll
                for (int j = 0; j < 4; j++)
                    acc[i][j] += a[i] * b[j];
        }
        __syncthreads();
    }
    #pragma unroll
    for (int i = 0; i < 4; i++) {
        float4 v = {acc[i][0], acc[i][1], acc[i][2], acc[i][3]};
        *(float4*)&g_gpart[(size_t)(kc * B + ty * 4 + i) * G4 + n0 + tx * 4] = v;
    }
}

// -------------------- fused LSTM(t-1) + attention(t) ------------------------
__global__ __launch_bounds__(256)
void k_step(const float* __restrict__ enc, const int* __restrict__ tgt,
            const float* __restrict__ emb, const float* __restrict__ W_dec,
            const float* __restrict__ b_att, const float* __restrict__ v_att,
            int t) {
    int b = blockIdx.x;
    int tid = threadIdx.x;
    __shared__ float sh_h[H];
    __shared__ float sh_dp[A_DIM];
    __shared__ float sh_v[A_DIM];
    __shared__ float sh_sc[S];

    // ---- LSTM elementwise for step t-1 ----
    if (t > 0) {
        #pragma unroll
        for (int jj = 0; jj < 2; jj++) {
            int j = tid + jj * 256;
            float gi = g_bf[j], gf = g_bf[j + H];
            float gg = g_bf[j + 2 * H], go = g_bf[j + 3 * H];
            #pragma unroll
            for (int p = 0; p < KSPLIT; p++) {
                const float* gp = &g_gpart[(size_t)(p * B + b) * G4];
                gi += gp[j];         gf += gp[j + H];
                gg += gp[j + 2 * H]; go += gp[j + 3 * H];
            }
            float c = g_c[b * H + j];
            float si = 1.f / (1.f + expf(-gi));
            float sf = 1.f / (1.f + expf(-gf));
            float so = 1.f / (1.f + expf(-go));
            float cn = sf * c + si * tanhf(gg);
            float hn = so * tanhf(cn);
            g_c[b * H + j] = cn;
            sh_h[j] = hn;
            g_xh[b * KG + KX + j] = hn;
            g_hcatall[(size_t)((t - 1) * B + b) * KX + j] = hn;
        }
    } else {
        sh_h[tid] = 0.f;
        sh_h[tid + 256] = 0.f;
    }
    if (t >= T) return;
    sh_v[tid] = v_att[tid];
    __syncthreads();

    // dp[a] = b_att[a] + h . W_dec[:,a]
    {
        float acc = b_att[tid];
        #pragma unroll 8
        for (int e = 0; e < H; e++) acc += sh_h[e] * W_dec[e * A_DIM + tid];
        sh_dp[tid] = acc;
    }
    __syncthreads();

    // scores (fast tanh)
    int warp = tid >> 5, lane = tid & 31;
    for (int s = warp; s < S; s += 8) {
        const float* ep = &g_encproj[((size_t)b * S + s) * A_DIM];
        float acc = 0.f;
        #pragma unroll
        for (int a = lane; a < A_DIM; a += 32)
            acc += tanh_fast(ep[a] + sh_dp[a]) * sh_v[a];
        #pragma unroll
        for (int o = 16; o; o >>= 1) acc += __shfl_xor_sync(0xffffffffu, acc, o);
        if (lane == 0) sh_sc[s] = acc;
    }
    __syncthreads();

    // softmax over S=128
    if (warp == 0) {
        float v0 = sh_sc[lane], v1 = sh_sc[lane + 32];
        float v2 = sh_sc[lane + 64], v3 = sh_sc[lane + 96];
        float m = fmaxf(fmaxf(v0, v1), fmaxf(v2, v3));
        #pragma unroll
        for (int o = 16; o; o >>= 1) m = fmaxf(m, __shfl_xor_sync(0xffffffffu, m, o));
        float e0 = __expf(v0 - m), e1 = __expf(v1 - m);
        float e2 = __expf(v2 - m), e3 = __expf(v3 - m);
        float sum = e0 + e1 + e2 + e3;
        #pragma unroll
        for (int o = 16; o; o >>= 1) sum += __shfl_xor_sync(0xffffffffu, sum, o);
        float inv = 1.f / sum;
        sh_sc[lane] = e0 * inv;        sh_sc[lane + 32] = e1 * inv;
        sh_sc[lane + 64] = e2 * inv;   sh_sc[lane + 96] = e3 * inv;
    }
    __syncthreads();

    // ctx
    for (int e = tid; e < E; e += 256) {
        float acc = 0.f;
        const float* eb = &enc[((size_t)b * S) * E + e];
        #pragma unroll 8
        for (int s = 0; s < S; s++) acc += sh_sc[s] * eb[(size_t)s * E];
        g_xh[b * KG + H + e] = acc;
        g_hcatall[(size_t)(t * B + b) * KX + H + e] = acc;
    }

    // x_emb
    int tok = (t == 0) ? 0 : tgt[b * T + t - 1];
    for (int j = tid; j < H; j += 256)
        g_xh[b * KG + j] = emb[(size_t)tok * H + j];
}

// -------------------- TF32 tensor-core output GEMM -------------------------
// [T*B=2048, V=8192] = hcat[2048,1024] @ W_out[8192,1024]^T + b_out
#define OBK 16
#define SSTR 20   // smem row stride in words (conflict-free for frag pattern)
__global__ __launch_bounds__(256, 2)
void k_out_mma(const float* __restrict__ Bw, const float* __restrict__ bias,
               float* __restrict__ out) {
    __shared__ unsigned As[128 * SSTR];
    __shared__ unsigned Bs[128 * SSTR];
    int tid = threadIdx.x;
    int lane = tid & 31, w = tid >> 5;
    int wm = w >> 2, wn = w & 3;            // warp grid 2(m) x 4(n)
    int m0 = blockIdx.y * 128, n0 = blockIdx.x * 128;

    int lrow = tid >> 1;                    // 0..127
    int lcol = (tid & 1) * 8;               // 0 or 8
    const float* Ag = &g_hcatall[(size_t)(m0 + lrow) * KX + lcol];
    const float* Bg = Bw + (size_t)(n0 + lrow) * KX + lcol;

    float acc[4][4][4] = {};
    int qr = lane >> 2;                     // 0..7
    int qc = lane & 3;                      // 0..3

    for (int k0 = 0; k0 < KX; k0 += OBK) {
        float4 a0 = *(const float4*)(Ag + k0);
        float4 a1 = *(const float4*)(Ag + k0 + 4);
        float4 b0 = *(const float4*)(Bg + k0);
        float4 b1 = *(const float4*)(Bg + k0 + 4);
        unsigned* ap = &As[lrow * SSTR + lcol];
        unsigned* bp = &Bs[lrow * SSTR + lcol];
        ap[0] = f2tf32(a0.x); ap[1] = f2tf32(a0.y);
        ap[2] = f2tf32(a0.z); ap[3] = f2tf32(a0.w);
        ap[4] = f2tf32(a1.x); ap[5] = f2tf32(a1.y);
        ap[6] = f2tf32(a1.z); ap[7] = f2tf32(a1.w);
        bp[0] = f2tf32(b0.x); bp[1] = f2tf32(b0.y);
        bp[2] = f2tf32(b0.z); bp[3] = f2tf32(b0.w);
        bp[4] = f2tf32(b1.x); bp[5] = f2tf32(b1.y);
        bp[6] = f2tf32(b1.z); bp[7] = f2tf32(b1.w);
        __syncthreads();

        #pragma unroll
        for (int ks = 0; ks < OBK; ks += 8) {
            unsigned afr[4][4], bfr[4][2];
            #pragma unroll
            for (int mt = 0; mt < 4; mt++) {
                int r = wm * 64 + mt * 16 + qr;
                int c = ks + qc;
                afr[mt][0] = As[r * SSTR + c];
                afr[mt][1] = As[(r + 8) * SSTR + c];
                afr[mt][2] = As[r * SSTR + c + 4];
                afr[mt][3] = As[(r + 8) * SSTR + c + 4];
            }
            #pragma unroll
            for (int nt = 0; nt < 4; nt++) {
                int n = wn * 32 + nt * 8 + qr;
                int c = ks + qc;
                bfr[nt][0] = Bs[n * SSTR + c];
                bfr[nt][1] = Bs[n * SSTR + c + 4];
            }
            #pragma unroll
            for (int mt = 0; mt < 4; mt++)
                #pragma unroll
                for (int nt = 0; nt < 4; nt++)
                    mma_tf32(acc[mt][nt], afr[mt], bfr[nt]);
        }
        __syncthreads();
    }

    // epilogue
    #pragma unroll
    for (int mt = 0; mt < 4; mt++) {
        #pragma unroll
        for (int nt = 0; nt < 4; nt++) {
            int ncol = n0 + wn * 32 + nt * 8 + qc * 2;
            float bz0 = bias[ncol], bz1 = bias[ncol + 1];
            #pragma unroll
            for (int half = 0; half < 2; half++) {
                int r = m0 + wm * 64 + mt * 16 + qr + half * 8;
                int bidx = r & (B - 1);
                int tt = r >> 6;
                float* o = out + (size_t)bidx * T * V + (size_t)tt * V + ncol;
                float2 v = {acc[mt][nt][half * 2 + 0] + bz0,
                            acc[mt][nt][half * 2 + 1] + bz1};
                *(float2*)o = v;
            }
        }
    }
}

// -------------------- launch ------------------------------------------------
extern "C" void kernel_launch(void* const* d_in, const int* in_sizes, int n_in,
                              void* d_out, int out_size) {
    const float* enc   = (const float*)d_in[0];
    const int*   tgt   = (const int*)  d_in[1];
    const float* emb   = (const float*)d_in[2];
    const float* W_enc = (const float*)d_in[3];
    const float* W_dec = (const float*)d_in[4];
    const float* b_att = (const float*)d_in[5];
    const float* v_att = (const float*)d_in[6];
    const float* W_ih  = (const float*)d_in[7];
    const float* W_hh  = (const float*)d_in[8];
    const float* b_ih  = (const float*)d_in[9];
    const float* b_hh  = (const float*)d_in[10];
    const float* W_out = (const float*)d_in[11];
    const float* b_out = (const float*)d_in[12];
    float* out = (float*)d_out;

    float *p_encproj, *p_WencT;
    cudaGetSymbolAddress((void**)&p_encproj, g_encproj);
    cudaGetSymbolAddress((void**)&p_WencT,   g_WencT);

    k_prep<<<512, 256>>>(W_enc, W_ih, W_hh, b_ih, b_hh);

    // enc_proj = enc[B*S, E] @ W_enc -> [B*S, A]
    {
        dim3 grid(A_DIM / BN, (B * S) / BM);
        k_gemm<<<grid, 256>>>(enc, p_WencT, p_encproj, B * S, A_DIM, E, A_DIM);
    }

    for (int t = 0; t < T; t++) {
        k_step<<<B, 256>>>(enc, tgt, emb, W_dec, b_att, v_att, t);
        dim3 grid(G4 / BN, KSPLIT);
        k_gates<<<grid, 256>>>();
    }
    // final LSTM (produces h_{T-1})
    k_step<<<B, 256>>>(enc, tgt, emb, W_dec, b_att, v_att, T);

    // one big tf32 output projection for all timesteps
    {
        dim3 grid(V / 128, (T * B) / 128);
        k_out_mma<<<grid, 256>>>(W_out, b_out, out);
    }
}

// round 4
// speedup vs baseline: 3.9738x; 1.2173x over previous
#include <cuda_runtime.h>
#include <math.h>

// Problem constants
#define B     64
#define S     128
#define E     512
#define H     512
#define A_DIM 256
#define V     8192
#define T     32
#define KX    1024   // H + E
#define KG    1536   // H + E + H
#define G4    2048   // 4*H
#define KSPLIT 8
#define KCHUNK (KG / KSPLIT)   // 192

// -------------------- scratch (device globals) -----------------------------
__device__ float    g_encproj[B * S * A_DIM];
__device__ unsigned g_WencT_hi[A_DIM * E];
__device__ unsigned g_WencT_lo[A_DIM * E];
__device__ unsigned g_Wf_hi[G4 * KG];
__device__ unsigned g_Wf_lo[G4 * KG];
__device__ float    g_bf[G4];
__device__ float    g_xh[B * KG];            // [emb | ctx | h_prev]
__device__ float    g_hcatall[T * B * KX];   // [h_t | ctx_t] all steps
__device__ float    g_c[B * H];
__device__ float    g_gpart[KSPLIT * B * G4];

// -------------------- helpers ----------------------------------------------
__device__ __forceinline__ unsigned f2tf32(float x) {
    unsigned r;
    asm("cvt.rna.tf32.f32 %0, %1;" : "=r"(r) : "f"(x));
    return r;
}
__device__ __forceinline__ float tanh_fast(float x) {
    float y;
    asm("tanh.approx.f32 %0, %1;" : "=f"(y) : "f"(x));
    return y;
}
__device__ __forceinline__ float sigmoid_fast(float x) {
    return __fdividef(1.f, 1.f + __expf(-x));
}
__device__ __forceinline__ void mma_tf32(float* d, const unsigned* a, const unsigned* b) {
    asm("mma.sync.aligned.m16n8k8.row.col.f32.tf32.tf32.f32 "
        "{%0,%1,%2,%3}, {%4,%5,%6,%7}, {%8,%9}, {%0,%1,%2,%3};"
        : "+f"(d[0]), "+f"(d[1]), "+f"(d[2]), "+f"(d[3])
        : "r"(a[0]), "r"(a[1]), "r"(a[2]), "r"(a[3]), "r"(b[0]), "r"(b[1]));
}

// -------------------- setup: split weights into tf32 hi/lo -----------------
__global__ void k_prep(const float* __restrict__ W_enc,
                       const float* __restrict__ W_ih,
                       const float* __restrict__ W_hh,
                       const float* __restrict__ b_ih,
                       const float* __restrict__ b_hh) {
    int stride = gridDim.x * blockDim.x;
    int tid0 = blockIdx.x * blockDim.x + threadIdx.x;
    for (int i = tid0; i < A_DIM * E; i += stride) {
        int a = i / E, e = i % E;
        float v = W_enc[e * A_DIM + a];
        unsigned hi = f2tf32(v);
        g_WencT_hi[i] = hi;
        g_WencT_lo[i] = f2tf32(v - __uint_as_float(hi));
    }
    for (int i = tid0; i < G4 * KG; i += stride) {
        int j = i / KG, k = i % KG;
        float v = (k < KX) ? W_ih[j * KX + k] : W_hh[j * H + (k - KX)];
        unsigned hi = f2tf32(v);
        g_Wf_hi[i] = hi;
        g_Wf_lo[i] = f2tf32(v - __uint_as_float(hi));
    }
    for (int i = tid0; i < G4; i += stride) g_bf[i] = b_ih[i] + b_hh[i];
    for (int i = tid0; i < B * H; i += stride) {
        g_c[i] = 0.0f;
        int b = i / H, j = i % H;
        g_xh[b * KG + KX + j] = 0.0f;   // h0 = 0
    }
}

// -------------------- split-TF32 tensor-core GEMM --------------------------
// C[m0:m0+64, n0:n0+128] (+ z-partial) = A[fp32, lda] @ B[hi/lo tf32, ldb]^T
// A is split into hi/lo in-kernel (3 MMA products: hh + hl + lh).
#define MSTR 20
__global__ __launch_bounds__(256, 2)
void k_mma_split(const float* __restrict__ A, int lda,
                 const unsigned* __restrict__ Bhi,
                 const unsigned* __restrict__ Blo, int ldb,
                 float* __restrict__ C, int ldc, size_t czstride,
                 int kchunk) {
    __shared__ unsigned Ah[64 * MSTR], Al[64 * MSTR];
    __shared__ unsigned Bh[128 * MSTR], Bl[128 * MSTR];
    int tid = threadIdx.x;
    int lane = tid & 31, w = tid >> 5;
    int wm = w >> 2, wn = w & 3;              // 2 x 4 warps
    int qr = lane >> 2, qc = lane & 3;
    int m0 = blockIdx.y * 64, n0 = blockIdx.x * 128;
    int kbase = blockIdx.z * kchunk;

    // A loader: 64x16 floats, 4 per thread
    int ar = tid >> 2, ac = (tid & 3) * 4;
    const float* Ag = A + (size_t)(m0 + ar) * lda + kbase + ac;
    // B loader: 128x16 words, 8 per thread per array
    int br = tid >> 1, bc = (tid & 1) * 8;
    const unsigned* Bhg = Bhi + (size_t)(n0 + br) * ldb + kbase + bc;
    const unsigned* Blg = Blo + (size_t)(n0 + br) * ldb + kbase + bc;

    float acc[2][4][4] = {};

    int nk = kchunk >> 4;
    for (int kt = 0; kt < nk; kt++) {
        int koff = kt * 16;
        float4 av = *(const float4*)(Ag + koff);
        uint4 bh0 = *(const uint4*)(Bhg + koff);
        uint4 bh1 = *(const uint4*)(Bhg + koff + 4);
        uint4 bl0 = *(const uint4*)(Blg + koff);
        uint4 bl1 = *(const uint4*)(Blg + koff + 4);
        __syncthreads();
        {
            float a[4] = {av.x, av.y, av.z, av.w};
            #pragma unroll
            for (int i = 0; i < 4; i++) {
                unsigned hi = f2tf32(a[i]);
                Ah[ar * MSTR + ac + i] = hi;
                Al[ar * MSTR + ac + i] = f2tf32(a[i] - __uint_as_float(hi));
            }
            unsigned* bp = &Bh[br * MSTR + bc];
            bp[0] = bh0.x; bp[1] = bh0.y; bp[2] = bh0.z; bp[3] = bh0.w;
            bp[4] = bh1.x; bp[5] = bh1.y; bp[6] = bh1.z; bp[7] = bh1.w;
            unsigned* lp = &Bl[br * MSTR + bc];
            lp[0] = bl0.x; lp[1] = bl0.y; lp[2] = bl0.z; lp[3] = bl0.w;
            lp[4] = bl1.x; lp[5] = bl1.y; lp[6] = bl1.z; lp[7] = bl1.w;
        }
        __syncthreads();

        #pragma unroll
        for (int ks = 0; ks < 16; ks += 8) {
            unsigned ah[2][4], al[2][4], bhf[4][2], blf[4][2];
            #pragma unroll
            for (int mt = 0; mt < 2; mt++) {
                int r = wm * 32 + mt * 16 + qr;
                int c = ks + qc;
                ah[mt][0] = Ah[r * MSTR + c];
                ah[mt][1] = Ah[(r + 8) * MSTR + c];
                ah[mt][2] = Ah[r * MSTR + c + 4];
                ah[mt][3] = Ah[(r + 8) * MSTR + c + 4];
                al[mt][0] = Al[r * MSTR + c];
                al[mt][1] = Al[(r + 8) * MSTR + c];
                al[mt][2] = Al[r * MSTR + c + 4];
                al[mt][3] = Al[(r + 8) * MSTR + c + 4];
            }
            #pragma unroll
            for (int nt = 0; nt < 4; nt++) {
                int n = wn * 32 + nt * 8 + qr;
                int c = ks + qc;
                bhf[nt][0] = Bh[n * MSTR + c];
                bhf[nt][1] = Bh[n * MSTR + c + 4];
                blf[nt][0] = Bl[n * MSTR + c];
                blf[nt][1] = Bl[n * MSTR + c + 4];
            }
            #pragma unroll
            for (int mt = 0; mt < 2; mt++)
                #pragma unroll
                for (int nt = 0; nt < 4; nt++) {
                    mma_tf32(acc[mt][nt], ah[mt], bhf[nt]);
                    mma_tf32(acc[mt][nt], ah[mt], blf[nt]);
                    mma_tf32(acc[mt][nt], al[mt], bhf[nt]);
                }
        }
    }

    float* Cp = C + (size_t)blockIdx.z * czstride;
    #pragma unroll
    for (int mt = 0; mt < 2; mt++)
        #pragma unroll
        for (int nt = 0; nt < 4; nt++) {
            int col = n0 + wn * 32 + nt * 8 + qc * 2;
            #pragma unroll
            for (int half = 0; half < 2; half++) {
                int row = m0 + wm * 32 + mt * 16 + qr + half * 8;
                float2 v = {acc[mt][nt][half * 2 + 0],
                            acc[mt][nt][half * 2 + 1]};
                *(float2*)&Cp[(size_t)row * ldc + col] = v;
            }
        }
}

// -------------------- fused LSTM(t-1) + attention(t) ------------------------
__global__ __launch_bounds__(256)
void k_step(const float* __restrict__ enc, const int* __restrict__ tgt,
            const float* __restrict__ emb, const float* __restrict__ W_dec,
            const float* __restrict__ b_att, const float* __restrict__ v_att,
            int t) {
    int b = blockIdx.x;
    int tid = threadIdx.x;
    __shared__ float sh_h[H];
    __shared__ float sh_dp[A_DIM];
    __shared__ float sh_v[A_DIM];
    __shared__ float sh_sc[S];

    if (t > 0) {
        #pragma unroll
        for (int jj = 0; jj < 2; jj++) {
            int j = tid + jj * 256;
            float gi = g_bf[j], gf = g_bf[j + H];
            float gg = g_bf[j + 2 * H], go = g_bf[j + 3 * H];
            #pragma unroll
            for (int p = 0; p < KSPLIT; p++) {
                const float* gp = &g_gpart[(size_t)(p * B + b) * G4];
                gi += gp[j];         gf += gp[j + H];
                gg += gp[j + 2 * H]; go += gp[j + 3 * H];
            }
            float c = g_c[b * H + j];
            float cn = sigmoid_fast(gf) * c + sigmoid_fast(gi) * tanh_fast(gg);
            float hn = sigmoid_fast(go) * tanh_fast(cn);
            g_c[b * H + j] = cn;
            sh_h[j] = hn;
            g_xh[b * KG + KX + j] = hn;
            g_hcatall[(size_t)((t - 1) * B + b) * KX + j] = hn;
        }
    } else {
        sh_h[tid] = 0.f;
        sh_h[tid + 256] = 0.f;
    }
    if (t >= T) return;
    sh_v[tid] = v_att[tid];
    __syncthreads();

    // dp[a] = b_att[a] + h . W_dec[:,a]
    {
        float acc = b_att[tid];
        #pragma unroll 8
        for (int e = 0; e < H; e++) acc += sh_h[e] * W_dec[e * A_DIM + tid];
        sh_dp[tid] = acc;
    }
    __syncthreads();

    // scores
    int warp = tid >> 5, lane = tid & 31;
    for (int s = warp; s < S; s += 8) {
        const float* ep = &g_encproj[((size_t)b * S + s) * A_DIM];
        float acc = 0.f;
        #pragma unroll
        for (int a = lane; a < A_DIM; a += 32)
            acc += tanh_fast(ep[a] + sh_dp[a]) * sh_v[a];
        #pragma unroll
        for (int o = 16; o; o >>= 1) acc += __shfl_xor_sync(0xffffffffu, acc, o);
        if (lane == 0) sh_sc[s] = acc;
    }
    __syncthreads();

    // softmax
    if (warp == 0) {
        float v0 = sh_sc[lane], v1 = sh_sc[lane + 32];
        float v2 = sh_sc[lane + 64], v3 = sh_sc[lane + 96];
        float m = fmaxf(fmaxf(v0, v1), fmaxf(v2, v3));
        #pragma unroll
        for (int o = 16; o; o >>= 1) m = fmaxf(m, __shfl_xor_sync(0xffffffffu, m, o));
        float e0 = __expf(v0 - m), e1 = __expf(v1 - m);
        float e2 = __expf(v2 - m), e3 = __expf(v3 - m);
        float sum = e0 + e1 + e2 + e3;
        #pragma unroll
        for (int o = 16; o; o >>= 1) sum += __shfl_xor_sync(0xffffffffu, sum, o);
        float inv = __fdividef(1.f, sum);
        sh_sc[lane] = e0 * inv;        sh_sc[lane + 32] = e1 * inv;
        sh_sc[lane + 64] = e2 * inv;   sh_sc[lane + 96] = e3 * inv;
    }
    __syncthreads();

    // ctx
    for (int e = tid; e < E; e += 256) {
        float acc = 0.f;
        const float* eb = &enc[((size_t)b * S) * E + e];
        #pragma unroll 8
        for (int s = 0; s < S; s++) acc += sh_sc[s] * eb[(size_t)s * E];
        g_xh[b * KG + H + e] = acc;
        g_hcatall[(size_t)(t * B + b) * KX + H + e] = acc;
    }

    // x_emb
    int tok = (t == 0) ? 0 : tgt[b * T + t - 1];
    for (int j = tid; j < H; j += 256)
        g_xh[b * KG + j] = emb[(size_t)tok * H + j];
}

// -------------------- TF32 tensor-core output GEMM -------------------------
#define OBK 16
#define SSTR 20
__global__ __launch_bounds__(256, 2)
void k_out_mma(const float* __restrict__ Bw, const float* __restrict__ bias,
               float* __restrict__ out) {
    __shared__ unsigned As[128 * SSTR];
    __shared__ unsigned Bs[128 * SSTR];
    int tid = threadIdx.x;
    int lane = tid & 31, w = tid >> 5;
    int wm = w >> 2, wn = w & 3;
    int m0 = blockIdx.y * 128, n0 = blockIdx.x * 128;

    int lrow = tid >> 1;
    int lcol = (tid & 1) * 8;
    const float* Ag = &g_hcatall[(size_t)(m0 + lrow) * KX + lcol];
    const float* Bg = Bw + (size_t)(n0 + lrow) * KX + lcol;

    float acc[4][4][4] = {};
    int qr = lane >> 2, qc = lane & 3;

    for (int k0 = 0; k0 < KX; k0 += OBK) {
        float4 a0 = *(const float4*)(Ag + k0);
        float4 a1 = *(const float4*)(Ag + k0 + 4);
        float4 b0 = *(const float4*)(Bg + k0);
        float4 b1 = *(const float4*)(Bg + k0 + 4);
        unsigned* ap = &As[lrow * SSTR + lcol];
        unsigned* bp = &Bs[lrow * SSTR + lcol];
        ap[0] = f2tf32(a0.x); ap[1] = f2tf32(a0.y);
        ap[2] = f2tf32(a0.z); ap[3] = f2tf32(a0.w);
        ap[4] = f2tf32(a1.x); ap[5] = f2tf32(a1.y);
        ap[6] = f2tf32(a1.z); ap[7] = f2tf32(a1.w);
        bp[0] = f2tf32(b0.x); bp[1] = f2tf32(b0.y);
        bp[2] = f2tf32(b0.z); bp[3] = f2tf32(b0.w);
        bp[4] = f2tf32(b1.x); bp[5] = f2tf32(b1.y);
        bp[6] = f2tf32(b1.z); bp[7] = f2tf32(b1.w);
        __syncthreads();

        #pragma unroll
        for (int ks = 0; ks < OBK; ks += 8) {
            unsigned afr[4][4], bfr[4][2];
            #pragma unroll
            for (int mt = 0; mt < 4; mt++) {
                int r = wm * 64 + mt * 16 + qr;
                int c = ks + qc;
                afr[mt][0] = As[r * SSTR + c];
                afr[mt][1] = As[(r + 8) * SSTR + c];
                afr[mt][2] = As[r * SSTR + c + 4];
                afr[mt][3] = As[(r + 8) * SSTR + c + 4];
            }
            #pragma unroll
            for (int nt = 0; nt < 4; nt++) {
                int n = wn * 32 + nt * 8 + qr;
                int c = ks + qc;
                bfr[nt][0] = Bs[n * SSTR + c];
                bfr[nt][1] = Bs[n * SSTR + c + 4];
            }
            #pragma unroll
            for (int mt = 0; mt < 4; mt++)
                #pragma unroll
                for (int nt = 0; nt < 4; nt++)
                    mma_tf32(acc[mt][nt], afr[mt], bfr[nt]);
        }
        __syncthreads();
    }

    #pragma unroll
    for (int mt = 0; mt < 4; mt++) {
        #pragma unroll
        for (int nt = 0; nt < 4; nt++) {
            int ncol = n0 + wn * 32 + nt * 8 + qc * 2;
            float bz0 = bias[ncol], bz1 = bias[ncol + 1];
            #pragma unroll
            for (int half = 0; half < 2; half++) {
                int r = m0 + wm * 64 + mt * 16 + qr + half * 8;
                int bidx = r & (B - 1);
                int tt = r >> 6;
                float* o = out + (size_t)bidx * T * V + (size_t)tt * V + ncol;
                float2 v = {acc[mt][nt][half * 2 + 0] + bz0,
                            acc[mt][nt][half * 2 + 1] + bz1};
                *(float2*)o = v;
            }
        }
    }
}

// -------------------- launch ------------------------------------------------
extern "C" void kernel_launch(void* const* d_in, const int* in_sizes, int n_in,
                              void* d_out, int out_size) {
    const float* enc   = (const float*)d_in[0];
    const int*   tgt   = (const int*)  d_in[1];
    const float* emb   = (const float*)d_in[2];
    const float* W_enc = (const float*)d_in[3];
    const float* W_dec = (const float*)d_in[4];
    const float* b_att = (const float*)d_in[5];
    const float* v_att = (const float*)d_in[6];
    const float* W_ih  = (const float*)d_in[7];
    const float* W_hh  = (const float*)d_in[8];
    const float* b_ih  = (const float*)d_in[9];
    const float* b_hh  = (const float*)d_in[10];
    const float* W_out = (const float*)d_in[11];
    const float* b_out = (const float*)d_in[12];
    float* out = (float*)d_out;

    float *p_encproj, *p_xh, *p_gpart;
    unsigned *p_WencT_hi, *p_WencT_lo, *p_Wf_hi, *p_Wf_lo;
    cudaGetSymbolAddress((void**)&p_encproj,  g_encproj);
    cudaGetSymbolAddress((void**)&p_xh,       g_xh);
    cudaGetSymbolAddress((void**)&p_gpart,    g_gpart);
    cudaGetSymbolAddress((void**)&p_WencT_hi, g_WencT_hi);
    cudaGetSymbolAddress((void**)&p_WencT_lo, g_WencT_lo);
    cudaGetSymbolAddress((void**)&p_Wf_hi,    g_Wf_hi);
    cudaGetSymbolAddress((void**)&p_Wf_lo,    g_Wf_lo);

    k_prep<<<512, 256>>>(W_enc, W_ih, W_hh, b_ih, b_hh);

    // enc_proj[B*S, A] = enc[B*S, E] @ W_enc (split-tf32)
    {
        dim3 grid(A_DIM / 128, (B * S) / 64, 1);   // (2, 128, 1)
        k_mma_split<<<grid, 256>>>(enc, E, p_WencT_hi, p_WencT_lo, E,
                                   p_encproj, A_DIM, 0, E);
    }

    for (int t = 0; t < T; t++) {
        k_step<<<B, 256>>>(enc, tgt, emb, W_dec, b_att, v_att, t);
        // gates partials: [64, 2048] over K=1536 split into 8 chunks
        dim3 grid(G4 / 128, 1, KSPLIT);            // (16, 1, 8)
        k_mma_split<<<grid, 256>>>(p_xh, KG, p_Wf_hi, p_Wf_lo, KG,
                                   p_gpart, G4, (size_t)B * G4, KCHUNK);
    }
    k_step<<<B, 256>>>(enc, tgt, emb, W_dec, b_att, v_att, T);

    // output projection for all timesteps
    {
        dim3 grid(V / 128, (T * B) / 128);
        k_out_mma<<<grid, 256>>>(W_out, b_out, out);
    }
}

// round 5
// speedup vs baseline: 4.0432x; 1.0175x over previous
#include <cuda_runtime.h>
#include <math.h>

// Problem constants
#define B     64
#define S     128
#define E     512
#define H     512
#define A_DIM 256
#define V     8192
#define T     32
#define KX    1024   // H + E (out-proj input [h|ctx])
#define KC    1024   // per-step gates input [ctx|h]
#define G4    2048   // 4*H
#define KSPLIT 16
#define KCHUNK (KC / KSPLIT)   // 64

// -------------------- scratch (device globals) -----------------------------
__device__ float    g_encproj[B * S * A_DIM];
__device__ unsigned g_WencT_hi[A_DIM * E];
__device__ unsigned g_WencT_lo[A_DIM * E];
__device__ unsigned g_Wf_hi[G4 * KC];        // [ctx | h] weights
__device__ unsigned g_Wf_lo[G4 * KC];
__device__ unsigned g_We_hi[G4 * H];         // emb weights
__device__ unsigned g_We_lo[G4 * H];
__device__ float    g_bf[G4];
__device__ float    g_xh[B * KC];            // [ctx | h_prev]
__device__ float    g_xe[T * B * H];         // gathered embeddings, all steps
__device__ float    g_embpart[T * B * G4];   // emb @ We^T, all steps (16 MB)
__device__ float    g_hcatall[T * B * KX];   // [h_t | ctx_t] all steps
__device__ float    g_c[B * H];
__device__ float    g_gpart[KSPLIT * B * G4];

// -------------------- helpers ----------------------------------------------
__device__ __forceinline__ unsigned f2tf32(float x) {
    unsigned r;
    asm("cvt.rna.tf32.f32 %0, %1;" : "=r"(r) : "f"(x));
    return r;
}
__device__ __forceinline__ float tanh_fast(float x) {
    float y;
    asm("tanh.approx.f32 %0, %1;" : "=f"(y) : "f"(x));
    return y;
}
__device__ __forceinline__ float sigmoid_fast(float x) {
    return __fdividef(1.f, 1.f + __expf(-x));
}
__device__ __forceinline__ void mma_tf32(float* d, const unsigned* a, const unsigned* b) {
    asm("mma.sync.aligned.m16n8k8.row.col.f32.tf32.tf32.f32 "
        "{%0,%1,%2,%3}, {%4,%5,%6,%7}, {%8,%9}, {%0,%1,%2,%3};"
        : "+f"(d[0]), "+f"(d[1]), "+f"(d[2]), "+f"(d[3])
        : "r"(a[0]), "r"(a[1]), "r"(a[2]), "r"(a[3]), "r"(b[0]), "r"(b[1]));
}

// -------------------- setup -------------------------------------------------
__global__ void k_prep(const float* __restrict__ W_enc,
                       const float* __restrict__ W_ih,
                       const float* __restrict__ W_hh,
                       const float* __restrict__ b_ih,
                       const float* __restrict__ b_hh) {
    int stride = gridDim.x * blockDim.x;
    int tid0 = blockIdx.x * blockDim.x + threadIdx.x;
    for (int i = tid0; i < A_DIM * E; i += stride) {
        int a = i / E, e = i % E;
        float v = W_enc[e * A_DIM + a];
        unsigned hi = f2tf32(v);
        g_WencT_hi[i] = hi;
        g_WencT_lo[i] = f2tf32(v - __uint_as_float(hi));
    }
    // Wf: [G4, 1024] = [W_ih ctx-cols | W_hh];  We: [G4, 512] = W_ih emb-cols
    for (int i = tid0; i < G4 * KC; i += stride) {
        int j = i / KC, k = i % KC;
        float v = (k < H) ? W_ih[j * KX + H + k] : W_hh[j * H + (k - H)];
        unsigned hi = f2tf32(v);
        g_Wf_hi[i] = hi;
        g_Wf_lo[i] = f2tf32(v - __uint_as_float(hi));
    }
    for (int i = tid0; i < G4 * H; i += stride) {
        int j = i / H, k = i % H;
        float v = W_ih[j * KX + k];
        unsigned hi = f2tf32(v);
        g_We_hi[i] = hi;
        g_We_lo[i] = f2tf32(v - __uint_as_float(hi));
    }
    for (int i = tid0; i < G4; i += stride) g_bf[i] = b_ih[i] + b_hh[i];
    for (int i = tid0; i < B * H; i += stride) {
        g_c[i] = 0.0f;
        int b = i / H, j = i % H;
        g_xh[b * KC + H + j] = 0.0f;   // h0 = 0
    }
}

// gather embeddings for all timesteps (teacher forcing)
__global__ void k_gather(const int* __restrict__ tgt, const float* __restrict__ emb) {
    int idx = blockIdx.x * blockDim.x + threadIdx.x;   // over T*B*H
    if (idx >= T * B * H) return;
    int r = idx >> 9, k = idx & 511;
    int t = r >> 6, b = r & 63;
    int tok = (t == 0) ? 0 : tgt[b * T + t - 1];
    g_xe[idx] = emb[(size_t)tok * H + k];
}

// -------------------- split-TF32 tensor-core GEMM --------------------------
// C[64-row tile, 128-col tile] (+ z-partial) = A[fp32] @ B[hi/lo tf32]^T
#define MSTR 20
__global__ __launch_bounds__(256, 2)
void k_mma_split(const float* __restrict__ A, int lda,
                 const unsigned* __restrict__ Bhi,
                 const unsigned* __restrict__ Blo, int ldb,
                 float* __restrict__ C, int ldc, size_t czstride,
                 int kchunk) {
    __shared__ unsigned Ah[64 * MSTR], Al[64 * MSTR];
    __shared__ unsigned Bh[128 * MSTR], Bl[128 * MSTR];
    int tid = threadIdx.x;
    int lane = tid & 31, w = tid >> 5;
    int wm = w >> 2, wn = w & 3;
    int qr = lane >> 2, qc = lane & 3;
    int m0 = blockIdx.y * 64, n0 = blockIdx.x * 128;
    int kbase = blockIdx.z * kchunk;

    int ar = tid >> 2, ac = (tid & 3) * 4;
    const float* Ag = A + (size_t)(m0 + ar) * lda + kbase + ac;
    int br = tid >> 1, bc = (tid & 1) * 8;
    const unsigned* Bhg = Bhi + (size_t)(n0 + br) * ldb + kbase + bc;
    const unsigned* Blg = Blo + (size_t)(n0 + br) * ldb + kbase + bc;

    float acc[2][4][4] = {};
    int nk = kchunk >> 4;
    for (int kt = 0; kt < nk; kt++) {
        int koff = kt * 16;
        float4 av = *(const float4*)(Ag + koff);
        uint4 bh0 = *(const uint4*)(Bhg + koff);
        uint4 bh1 = *(const uint4*)(Bhg + koff + 4);
        uint4 bl0 = *(const uint4*)(Blg + koff);
        uint4 bl1 = *(const uint4*)(Blg + koff + 4);
        __syncthreads();
        {
            float a[4] = {av.x, av.y, av.z, av.w};
            #pragma unroll
            for (int i = 0; i < 4; i++) {
                unsigned hi = f2tf32(a[i]);
                Ah[ar * MSTR + ac + i] = hi;
                Al[ar * MSTR + ac + i] = f2tf32(a[i] - __uint_as_float(hi));
            }
            unsigned* bp = &Bh[br * MSTR + bc];
            bp[0] = bh0.x; bp[1] = bh0.y; bp[2] = bh0.z; bp[3] = bh0.w;
            bp[4] = bh1.x; bp[5] = bh1.y; bp[6] = bh1.z; bp[7] = bh1.w;
            unsigned* lp = &Bl[br * MSTR + bc];
            lp[0] = bl0.x; lp[1] = bl0.y; lp[2] = bl0.z; lp[3] = bl0.w;
            lp[4] = bl1.x; lp[5] = bl1.y; lp[6] = bl1.z; lp[7] = bl1.w;
        }
        __syncthreads();

        #pragma unroll
        for (int ks = 0; ks < 16; ks += 8) {
            unsigned ah[2][4], al[2][4], bhf[4][2], blf[4][2];
            #pragma unroll
            for (int mt = 0; mt < 2; mt++) {
                int r = wm * 32 + mt * 16 + qr;
                int c = ks + qc;
                ah[mt][0] = Ah[r * MSTR + c];
                ah[mt][1] = Ah[(r + 8) * MSTR + c];
                ah[mt][2] = Ah[r * MSTR + c + 4];
                ah[mt][3] = Ah[(r + 8) * MSTR + c + 4];
                al[mt][0] = Al[r * MSTR + c];
                al[mt][1] = Al[(r + 8) * MSTR + c];
                al[mt][2] = Al[r * MSTR + c + 4];
                al[mt][3] = Al[(r + 8) * MSTR + c + 4];
            }
            #pragma unroll
            for (int nt = 0; nt < 4; nt++) {
                int n = wn * 32 + nt * 8 + qr;
                int c = ks + qc;
                bhf[nt][0] = Bh[n * MSTR + c];
                bhf[nt][1] = Bh[n * MSTR + c + 4];
                blf[nt][0] = Bl[n * MSTR + c];
                blf[nt][1] = Bl[n * MSTR + c + 4];
            }
            #pragma unroll
            for (int mt = 0; mt < 2; mt++)
                #pragma unroll
                for (int nt = 0; nt < 4; nt++) {
                    mma_tf32(acc[mt][nt], ah[mt], bhf[nt]);
                    mma_tf32(acc[mt][nt], ah[mt], blf[nt]);
                    mma_tf32(acc[mt][nt], al[mt], bhf[nt]);
                }
        }
    }

    float* Cp = C + (size_t)blockIdx.z * czstride;
    #pragma unroll
    for (int mt = 0; mt < 2; mt++)
        #pragma unroll
        for (int nt = 0; nt < 4; nt++) {
            int col = n0 + wn * 32 + nt * 8 + qc * 2;
            #pragma unroll
            for (int half = 0; half < 2; half++) {
                int row = m0 + wm * 32 + mt * 16 + qr + half * 8;
                float2 v = {acc[mt][nt][half * 2 + 0],
                            acc[mt][nt][half * 2 + 1]};
                *(float2*)&Cp[(size_t)row * ldc + col] = v;
            }
        }
}

// -------------------- fused LSTM(t-1) + attention(t) ------------------------
__global__ __launch_bounds__(256)
void k_step(const float* __restrict__ enc, const float* __restrict__ W_dec,
            const float* __restrict__ b_att, const float* __restrict__ v_att,
            int t) {
    int b = blockIdx.x;
    int tid = threadIdx.x;
    __shared__ float sh_h[H];
    __shared__ float sh_dp[A_DIM];
    __shared__ float sh_v[A_DIM];
    __shared__ float sh_sc[S];

    if (t > 0) {
        const float* ep = &g_embpart[(size_t)((t - 1) * B + b) * G4];
        #pragma unroll
        for (int jj = 0; jj < 2; jj++) {
            int j = tid + jj * 256;
            float gi = g_bf[j] + ep[j];
            float gf = g_bf[j + H] + ep[j + H];
            float gg = g_bf[j + 2 * H] + ep[j + 2 * H];
            float go = g_bf[j + 3 * H] + ep[j + 3 * H];
            #pragma unroll
            for (int p = 0; p < KSPLIT; p++) {
                const float* gp = &g_gpart[(size_t)(p * B + b) * G4];
                gi += gp[j];         gf += gp[j + H];
                gg += gp[j + 2 * H]; go += gp[j + 3 * H];
            }
            float c = g_c[b * H + j];
            float cn = sigmoid_fast(gf) * c + sigmoid_fast(gi) * tanh_fast(gg);
            float hn = sigmoid_fast(go) * tanh_fast(cn);
            g_c[b * H + j] = cn;
            sh_h[j] = hn;
            g_xh[b * KC + H + j] = hn;
            g_hcatall[(size_t)((t - 1) * B + b) * KX + j] = hn;
        }
    } else {
        sh_h[tid] = 0.f;
        sh_h[tid + 256] = 0.f;
    }
    if (t >= T) return;
    sh_v[tid] = v_att[tid];
    __syncthreads();

    // dp[a] = b_att[a] + h . W_dec[:,a]
    {
        float acc = b_att[tid];
        #pragma unroll 8
        for (int e = 0; e < H; e++) acc += sh_h[e] * W_dec[e * A_DIM + tid];
        sh_dp[tid] = acc;
    }
    __syncthreads();

    // scores
    int warp = tid >> 5, lane = tid & 31;
    for (int s = warp; s < S; s += 8) {
        const float* ep2 = &g_encproj[((size_t)b * S + s) * A_DIM];
        float acc = 0.f;
        #pragma unroll
        for (int a = lane; a < A_DIM; a += 32)
            acc += tanh_fast(ep2[a] + sh_dp[a]) * sh_v[a];
        #pragma unroll
        for (int o = 16; o; o >>= 1) acc += __shfl_xor_sync(0xffffffffu, acc, o);
        if (lane == 0) sh_sc[s] = acc;
    }
    __syncthreads();

    // softmax
    if (warp == 0) {
        float v0 = sh_sc[lane], v1 = sh_sc[lane + 32];
        float v2 = sh_sc[lane + 64], v3 = sh_sc[lane + 96];
        float m = fmaxf(fmaxf(v0, v1), fmaxf(v2, v3));
        #pragma unroll
        for (int o = 16; o; o >>= 1) m = fmaxf(m, __shfl_xor_sync(0xffffffffu, m, o));
        float e0 = __expf(v0 - m), e1 = __expf(v1 - m);
        float e2 = __expf(v2 - m), e3 = __expf(v3 - m);
        float sum = e0 + e1 + e2 + e3;
        #pragma unroll
        for (int o = 16; o; o >>= 1) sum += __shfl_xor_sync(0xffffffffu, sum, o);
        float inv = __fdividef(1.f, sum);
        sh_sc[lane] = e0 * inv;        sh_sc[lane + 32] = e1 * inv;
        sh_sc[lane + 64] = e2 * inv;   sh_sc[lane + 96] = e3 * inv;
    }
    __syncthreads();

    // ctx
    for (int e = tid; e < E; e += 256) {
        float acc = 0.f;
        const float* eb = &enc[((size_t)b * S) * E + e];
        #pragma unroll 8
        for (int s = 0; s < S; s++) acc += sh_sc[s] * eb[(size_t)s * E];
        g_xh[b * KC + e] = acc;                            // [ctx | h]
        g_hcatall[(size_t)(t * B + b) * KX + H + e] = acc; // [h | ctx]
    }
}

// -------------------- TF32 tensor-core output GEMM (OBK=32) ----------------
#define OBK 32
#define SSTR 36
__global__ __launch_bounds__(256, 2)
void k_out_mma(const float* __restrict__ Bw, const float* __restrict__ bias,
               float* __restrict__ out) {
    __shared__ unsigned As[128 * SSTR];
    __shared__ unsigned Bs[128 * SSTR];
    int tid = threadIdx.x;
    int lane = tid & 31, w = tid >> 5;
    int wm = w >> 2, wn = w & 3;
    int m0 = blockIdx.y * 128, n0 = blockIdx.x * 128;

    int lrow = tid >> 1;
    int lcol = (tid & 1) * 16;
    const float* Ag = &g_hcatall[(size_t)(m0 + lrow) * KX + lcol];
    const float* Bg = Bw + (size_t)(n0 + lrow) * KX + lcol;

    float acc[4][4][4] = {};
    int qr = lane >> 2, qc = lane & 3;

    for (int k0 = 0; k0 < KX; k0 += OBK) {
        float4 a0 = *(const float4*)(Ag + k0);
        float4 a1 = *(const float4*)(Ag + k0 + 4);
        float4 a2 = *(const float4*)(Ag + k0 + 8);
        float4 a3 = *(const float4*)(Ag + k0 + 12);
        float4 b0 = *(const float4*)(Bg + k0);
        float4 b1 = *(const float4*)(Bg + k0 + 4);
        float4 b2 = *(const float4*)(Bg + k0 + 8);
        float4 b3 = *(const float4*)(Bg + k0 + 12);
        __syncthreads();
        {
            unsigned* ap = &As[lrow * SSTR + lcol];
            ap[0]  = f2tf32(a0.x); ap[1]  = f2tf32(a0.y);
            ap[2]  = f2tf32(a0.z); ap[3]  = f2tf32(a0.w);
            ap[4]  = f2tf32(a1.x); ap[5]  = f2tf32(a1.y);
            ap[6]  = f2tf32(a1.z); ap[7]  = f2tf32(a1.w);
            ap[8]  = f2tf32(a2.x); ap[9]  = f2tf32(a2.y);
            ap[10] = f2tf32(a2.z); ap[11] = f2tf32(a2.w);
            ap[12] = f2tf32(a3.x); ap[13] = f2tf32(a3.y);
            ap[14] = f2tf32(a3.z); ap[15] = f2tf32(a3.w);
            unsigned* bp = &Bs[lrow * SSTR + lcol];
            bp[0]  = f2tf32(b0.x); bp[1]  = f2tf32(b0.y);
            bp[2]  = f2tf32(b0.z); bp[3]  = f2tf32(b0.w);
            bp[4]  = f2tf32(b1.x); bp[5]  = f2tf32(b1.y);
            bp[6]  = f2tf32(b1.z); bp[7]  = f2tf32(b1.w);
            bp[8]  = f2tf32(b2.x); bp[9]  = f2tf32(b2.y);
            bp[10] = f2tf32(b2.z); bp[11] = f2tf32(b2.w);
            bp[12] = f2tf32(b3.x); bp[13] = f2tf32(b3.y);
            bp[14] = f2tf32(b3.z); bp[15] = f2tf32(b3.w);
        }
        __syncthreads();

        #pragma unroll
        for (int ks = 0; ks < OBK; ks += 8) {
            unsigned afr[4][4], bfr[4][2];
            #pragma unroll
            for (int mt = 0; mt < 4; mt++) {
                int r = wm * 64 + mt * 16 + qr;
                int c = ks + qc;
                afr[mt][0] = As[r * SSTR + c];
                afr[mt][1] = As[(r + 8) * SSTR + c];
                afr[mt][2] = As[r * SSTR + c + 4];
                afr[mt][3] = As[(r + 8) * SSTR + c + 4];
            }
            #pragma unroll
            for (int nt = 0; nt < 4; nt++) {
                int n = wn * 32 + nt * 8 + qr;
                int c = ks + qc;
                bfr[nt][0] = Bs[n * SSTR + c];
                bfr[nt][1] = Bs[n * SSTR + c + 4];
            }
            #pragma unroll
            for (int mt = 0; mt < 4; mt++)
                #pragma unroll
                for (int nt = 0; nt < 4; nt++)
                    mma_tf32(acc[mt][nt], afr[mt], bfr[nt]);
        }
    }

    #pragma unroll
    for (int mt = 0; mt < 4; mt++) {
        #pragma unroll
        for (int nt = 0; nt < 4; nt++) {
            int ncol = n0 + wn * 32 + nt * 8 + qc * 2;
            float bz0 = bias[ncol], bz1 = bias[ncol + 1];
            #pragma unroll
            for (int half = 0; half < 2; half++) {
                int r = m0 + wm * 64 + mt * 16 + qr + half * 8;
                int bidx = r & (B - 1);
                int tt = r >> 6;
                float* o = out + (size_t)bidx * T * V + (size_t)tt * V + ncol;
                float2 v = {acc[mt][nt][half * 2 + 0] + bz0,
                            acc[mt][nt][half * 2 + 1] + bz1};
                *(float2*)o = v;
            }
        }
    }
}

// -------------------- launch ------------------------------------------------
extern "C" void kernel_launch(void* const* d_in, const int* in_sizes, int n_in,
                              void* d_out, int out_size) {
    const float* enc   = (const float*)d_in[0];
    const int*   tgt   = (const int*)  d_in[1];
    const float* emb   = (const float*)d_in[2];
    const float* W_enc = (const float*)d_in[3];
    const float* W_dec = (const float*)d_in[4];
    const float* b_att = (const float*)d_in[5];
    const float* v_att = (const float*)d_in[6];
    const float* W_ih  = (const float*)d_in[7];
    const float* W_hh  = (const float*)d_in[8];
    const float* b_ih  = (const float*)d_in[9];
    const float* b_hh  = (const float*)d_in[10];
    const float* W_out = (const float*)d_in[11];
    const float* b_out = (const float*)d_in[12];
    float* out = (float*)d_out;

    float *p_encproj, *p_xh, *p_xe, *p_embpart, *p_gpart;
    unsigned *p_WencT_hi, *p_WencT_lo, *p_Wf_hi, *p_Wf_lo, *p_We_hi, *p_We_lo;
    cudaGetSymbolAddress((void**)&p_encproj,  g_encproj);
    cudaGetSymbolAddress((void**)&p_xh,       g_xh);
    cudaGetSymbolAddress((void**)&p_xe,       g_xe);
    cudaGetSymbolAddress((void**)&p_embpart,  g_embpart);
    cudaGetSymbolAddress((void**)&p_gpart,    g_gpart);
    cudaGetSymbolAddress((void**)&p_WencT_hi, g_WencT_hi);
    cudaGetSymbolAddress((void**)&p_WencT_lo, g_WencT_lo);
    cudaGetSymbolAddress((void**)&p_Wf_hi,    g_Wf_hi);
    cudaGetSymbolAddress((void**)&p_Wf_lo,    g_Wf_lo);
    cudaGetSymbolAddress((void**)&p_We_hi,    g_We_hi);
    cudaGetSymbolAddress((void**)&p_We_lo,    g_We_lo);

    k_prep<<<512, 256>>>(W_enc, W_ih, W_hh, b_ih, b_hh);
    k_gather<<<(T * B * H + 255) / 256, 256>>>(tgt, emb);

    // enc_proj[B*S, A] = enc @ W_enc (split-tf32)
    {
        dim3 grid(A_DIM / 128, (B * S) / 64, 1);
        k_mma_split<<<grid, 256>>>(enc, E, p_WencT_hi, p_WencT_lo, E,
                                   p_encproj, A_DIM, 0, E);
    }
    // embpart[T*B, G4] = xe @ We^T (split-tf32), once for all steps
    {
        dim3 grid(G4 / 128, (T * B) / 64, 1);
        k_mma_split<<<grid, 256>>>(p_xe, H, p_We_hi, p_We_lo, H,
                                   p_embpart, G4, 0, H);
    }

    for (int t = 0; t < T; t++) {
        k_step<<<B, 256>>>(enc, W_dec, b_att, v_att, t);
        // gates partials: [64, 2048] over K=1024, split 16
        dim3 grid(G4 / 128, 1, KSPLIT);
        k_mma_split<<<grid, 256>>>(p_xh, KC, p_Wf_hi, p_Wf_lo, KC,
                                   p_gpart, G4, (size_t)B * G4, KCHUNK);
    }
    k_step<<<B, 256>>>(enc, W_dec, b_att, v_att, T);

    // output projection for all timesteps
    {
        dim3 grid(V / 128, (T * B) / 128);
        k_out_mma<<<grid, 256>>>(W_out, b_out, out);
    }
}

// round 6
// speedup vs baseline: 4.4376x; 1.0975x over previous
#include <cuda_runtime.h>
#include <math.h>

// Problem constants
#define B     64
#define S     128
#define E     512
#define H     512
#define A_DIM 256
#define V     8192
#define T     32
#define KX    1024   // H + E (out-proj input [h|ctx])
#define KC    1024   // per-step gates input [ctx|h]
#define G4    2048   // 4*H
#define KSPLIT 8
#define KCHUNK (KC / KSPLIT)   // 128
#define NB    128    // persistent grid size

// -------------------- scratch (device globals) -----------------------------
__device__ float    g_encproj[B * S * A_DIM];
__device__ unsigned g_WencT_hi[A_DIM * E];
__device__ unsigned g_WencT_lo[A_DIM * E];
__device__ unsigned g_Wf_hi[G4 * KC];        // [ctx | h] weights
__device__ unsigned g_Wf_lo[G4 * KC];
__device__ unsigned g_We_hi[G4 * H];         // emb weights
__device__ unsigned g_We_lo[G4 * H];
__device__ float    g_bf[G4];
__device__ float    g_xh[B * KC];            // [ctx | h_prev]
__device__ float    g_xe[T * B * H];         // gathered embeddings
__device__ float    g_embpart[T * B * G4];   // emb @ We^T, all steps
__device__ float    g_hcatall[T * B * KX];   // [h_t | ctx_t] all steps
__device__ float    g_c[B * H];
__device__ float    g_gpart[KSPLIT * B * G4];
__device__ unsigned g_bar_count = 0;
__device__ unsigned g_bar_phase = 0;

// -------------------- helpers ----------------------------------------------
__device__ __forceinline__ unsigned f2tf32(float x) {
    unsigned r;
    asm("cvt.rna.tf32.f32 %0, %1;" : "=r"(r) : "f"(x));
    return r;
}
__device__ __forceinline__ float tanh_fast(float x) {
    float y;
    asm("tanh.approx.f32 %0, %1;" : "=f"(y) : "f"(x));
    return y;
}
__device__ __forceinline__ float sigmoid_fast(float x) {
    return __fdividef(1.f, 1.f + __expf(-x));
}
__device__ __forceinline__ void mma_tf32(float* d, const unsigned* a, const unsigned* b) {
    asm("mma.sync.aligned.m16n8k8.row.col.f32.tf32.tf32.f32 "
        "{%0,%1,%2,%3}, {%4,%5,%6,%7}, {%8,%9}, {%0,%1,%2,%3};"
        : "+f"(d[0]), "+f"(d[1]), "+f"(d[2]), "+f"(d[3])
        : "r"(a[0]), "r"(a[1]), "r"(a[2]), "r"(a[3]), "r"(b[0]), "r"(b[1]));
}

__device__ __forceinline__ void grid_barrier() {
    __syncthreads();
    if (threadIdx.x == 0) {
        __threadfence();
        unsigned gen = *((volatile unsigned*)&g_bar_phase);
        if (atomicAdd(&g_bar_count, 1u) == NB - 1) {
            *((volatile unsigned*)&g_bar_count) = 0;
            __threadfence();
            *((volatile unsigned*)&g_bar_phase) = gen + 1;
        } else {
            while (*((volatile unsigned*)&g_bar_phase) == gen) {}
        }
        __threadfence();
    }
    __syncthreads();
}

// -------------------- setup (incl. embedding gather) -----------------------
__global__ void k_prep(const float* __restrict__ W_enc,
                       const float* __restrict__ W_ih,
                       const float* __restrict__ W_hh,
                       const float* __restrict__ b_ih,
                       const float* __restrict__ b_hh,
                       const int* __restrict__ tgt,
                       const float* __restrict__ emb) {
    int stride = gridDim.x * blockDim.x;
    int tid0 = blockIdx.x * blockDim.x + threadIdx.x;
    for (int i = tid0; i < A_DIM * E; i += stride) {
        int a = i / E, e = i % E;
        float v = W_enc[e * A_DIM + a];
        unsigned hi = f2tf32(v);
        g_WencT_hi[i] = hi;
        g_WencT_lo[i] = f2tf32(v - __uint_as_float(hi));
    }
    for (int i = tid0; i < G4 * KC; i += stride) {
        int j = i / KC, k = i % KC;
        float v = (k < H) ? W_ih[j * KX + H + k] : W_hh[j * H + (k - H)];
        unsigned hi = f2tf32(v);
        g_Wf_hi[i] = hi;
        g_Wf_lo[i] = f2tf32(v - __uint_as_float(hi));
    }
    for (int i = tid0; i < G4 * H; i += stride) {
        int j = i / H, k = i % H;
        float v = W_ih[j * KX + k];
        unsigned hi = f2tf32(v);
        g_We_hi[i] = hi;
        g_We_lo[i] = f2tf32(v - __uint_as_float(hi));
    }
    for (int i = tid0; i < G4; i += stride) g_bf[i] = b_ih[i] + b_hh[i];
    for (int i = tid0; i < B * H; i += stride) {
        g_c[i] = 0.0f;
        int b = i / H, j = i % H;
        g_xh[b * KC + H + j] = 0.0f;   // h0 = 0
    }
    for (int i = tid0; i < T * B * H; i += stride) {
        int r = i >> 9, k = i & 511;
        int t = r >> 6, b = r & 63;
        int tok = (t == 0) ? 0 : tgt[b * T + t - 1];
        g_xe[i] = emb[(size_t)tok * H + k];
    }
}

// -------------------- split-TF32 tensor-core GEMM (standalone) -------------
#define MSTR 20
__global__ __launch_bounds__(256, 2)
void k_mma_split(const float* __restrict__ A, int lda,
                 const unsigned* __restrict__ Bhi,
                 const unsigned* __restrict__ Blo, int ldb,
                 float* __restrict__ C, int ldc, size_t czstride,
                 int kchunk) {
    __shared__ unsigned Ah[64 * MSTR], Al[64 * MSTR];
    __shared__ unsigned Bh[128 * MSTR], Bl[128 * MSTR];
    int tid = threadIdx.x;
    int lane = tid & 31, w = tid >> 5;
    int wm = w >> 2, wn = w & 3;
    int qr = lane >> 2, qc = lane & 3;
    int m0 = blockIdx.y * 64, n0 = blockIdx.x * 128;
    int kbase = blockIdx.z * kchunk;

    int ar = tid >> 2, ac = (tid & 3) * 4;
    const float* Ag = A + (size_t)(m0 + ar) * lda + kbase + ac;
    int br = tid >> 1, bc = (tid & 1) * 8;
    const unsigned* Bhg = Bhi + (size_t)(n0 + br) * ldb + kbase + bc;
    const unsigned* Blg = Blo + (size_t)(n0 + br) * ldb + kbase + bc;

    float acc[2][4][4] = {};
    int nk = kchunk >> 4;
    for (int kt = 0; kt < nk; kt++) {
        int koff = kt * 16;
        float4 av = *(const float4*)(Ag + koff);
        uint4 bh0 = *(const uint4*)(Bhg + koff);
        uint4 bh1 = *(const uint4*)(Bhg + koff + 4);
        uint4 bl0 = *(const uint4*)(Blg + koff);
        uint4 bl1 = *(const uint4*)(Blg + koff + 4);
        __syncthreads();
        {
            float a[4] = {av.x, av.y, av.z, av.w};
            #pragma unroll
            for (int i = 0; i < 4; i++) {
                unsigned hi = f2tf32(a[i]);
                Ah[ar * MSTR + ac + i] = hi;
                Al[ar * MSTR + ac + i] = f2tf32(a[i] - __uint_as_float(hi));
            }
            unsigned* bp = &Bh[br * MSTR + bc];
            bp[0] = bh0.x; bp[1] = bh0.y; bp[2] = bh0.z; bp[3] = bh0.w;
            bp[4] = bh1.x; bp[5] = bh1.y; bp[6] = bh1.z; bp[7] = bh1.w;
            unsigned* lp = &Bl[br * MSTR + bc];
            lp[0] = bl0.x; lp[1] = bl0.y; lp[2] = bl0.z; lp[3] = bl0.w;
            lp[4] = bl1.x; lp[5] = bl1.y; lp[6] = bl1.z; lp[7] = bl1.w;
        }
        __syncthreads();

        #pragma unroll
        for (int ks = 0; ks < 16; ks += 8) {
            unsigned ah[2][4], al[2][4], bhf[4][2], blf[4][2];
            #pragma unroll
            for (int mt = 0; mt < 2; mt++) {
                int r = wm * 32 + mt * 16 + qr;
                int c = ks + qc;
                ah[mt][0] = Ah[r * MSTR + c];
                ah[mt][1] = Ah[(r + 8) * MSTR + c];
                ah[mt][2] = Ah[r * MSTR + c + 4];
                ah[mt][3] = Ah[(r + 8) * MSTR + c + 4];
                al[mt][0] = Al[r * MSTR + c];
                al[mt][1] = Al[(r + 8) * MSTR + c];
                al[mt][2] = Al[r * MSTR + c + 4];
                al[mt][3] = Al[(r + 8) * MSTR + c + 4];
            }
            #pragma unroll
            for (int nt = 0; nt < 4; nt++) {
                int n = wn * 32 + nt * 8 + qr;
                int c = ks + qc;
                bhf[nt][0] = Bh[n * MSTR + c];
                bhf[nt][1] = Bh[n * MSTR + c + 4];
                blf[nt][0] = Bl[n * MSTR + c];
                blf[nt][1] = Bl[n * MSTR + c + 4];
            }
            #pragma unroll
            for (int mt = 0; mt < 2; mt++)
                #pragma unroll
                for (int nt = 0; nt < 4; nt++) {
                    mma_tf32(acc[mt][nt], ah[mt], bhf[nt]);
                    mma_tf32(acc[mt][nt], ah[mt], blf[nt]);
                    mma_tf32(acc[mt][nt], al[mt], bhf[nt]);
                }
        }
    }

    float* Cp = C + (size_t)blockIdx.z * czstride;
    #pragma unroll
    for (int mt = 0; mt < 2; mt++)
        #pragma unroll
        for (int nt = 0; nt < 4; nt++) {
            int col = n0 + wn * 32 + nt * 8 + qc * 2;
            #pragma unroll
            for (int half = 0; half < 2; half++) {
                int row = m0 + wm * 32 + mt * 16 + qr + half * 8;
                float2 v = {acc[mt][nt][half * 2 + 0],
                            acc[mt][nt][half * 2 + 1]};
                *(float2*)&Cp[(size_t)row * ldc + col] = v;
            }
        }
}

// -------------------- persistent step loop ---------------------------------
// grid = 128 blocks x 256 threads, all co-resident (1 block/SM).
// Phase A (blocks 0..63): LSTM(t-1) + attention(t). Phase B (all): gates MMA.
#define SMEM_WORDS (64 * MSTR * 2 + 128 * MSTR * 2)   // 7680 words = 30 KB
__global__ __launch_bounds__(256, 1)
void k_loop(const float* __restrict__ enc, const float* __restrict__ W_dec,
            const float* __restrict__ b_att, const float* __restrict__ v_att) {
    __shared__ __align__(16) unsigned smem_u[SMEM_WORDS];
    int tid = threadIdx.x;
    int lane = tid & 31, warp = tid >> 5;

    for (int t = 0; t <= T; t++) {
        // ---------------- Phase A ----------------
        if (blockIdx.x < B) {
            int b = blockIdx.x;
            float* sh_h  = (float*)smem_u;          // 512
            float* sh_dp = sh_h + 512;              // 256
            float* sh_v  = sh_dp + 256;             // 256
            float* sh_sc = sh_v + 256;              // 128

            if (t > 0) {
                const float* ep = &g_embpart[(size_t)((t - 1) * B + b) * G4];
                #pragma unroll
                for (int jj = 0; jj < 2; jj++) {
                    int j = tid + jj * 256;
                    float gi = g_bf[j] + ep[j];
                    float gf = g_bf[j + H] + ep[j + H];
                    float gg = g_bf[j + 2 * H] + ep[j + 2 * H];
                    float go = g_bf[j + 3 * H] + ep[j + 3 * H];
                    #pragma unroll
                    for (int p = 0; p < KSPLIT; p++) {
                        const float* gp = &g_gpart[(size_t)(p * B + b) * G4];
                        gi += gp[j];         gf += gp[j + H];
                        gg += gp[j + 2 * H]; go += gp[j + 3 * H];
                    }
                    float c = g_c[b * H + j];
                    float cn = sigmoid_fast(gf) * c + sigmoid_fast(gi) * tanh_fast(gg);
                    float hn = sigmoid_fast(go) * tanh_fast(cn);
                    g_c[b * H + j] = cn;
                    sh_h[j] = hn;
                    g_xh[b * KC + H + j] = hn;
                    g_hcatall[(size_t)((t - 1) * B + b) * KX + j] = hn;
                }
            } else {
                sh_h[tid] = 0.f;
                sh_h[tid + 256] = 0.f;
            }
            if (t < T) {
                sh_v[tid] = v_att[tid];
                __syncthreads();

                // dp[a] = b_att[a] + h . W_dec[:,a]
                {
                    float acc = b_att[tid];
                    #pragma unroll 8
                    for (int e = 0; e < H; e++) acc += sh_h[e] * W_dec[e * A_DIM + tid];
                    sh_dp[tid] = acc;
                }
                __syncthreads();

                // scores
                for (int s = warp; s < S; s += 8) {
                    const float* ep2 = &g_encproj[((size_t)b * S + s) * A_DIM];
                    float acc = 0.f;
                    #pragma unroll
                    for (int a = lane; a < A_DIM; a += 32)
                        acc += tanh_fast(ep2[a] + sh_dp[a]) * sh_v[a];
                    #pragma unroll
                    for (int o = 16; o; o >>= 1)
                        acc += __shfl_xor_sync(0xffffffffu, acc, o);
                    if (lane == 0) sh_sc[s] = acc;
                }
                __syncthreads();

                // softmax
                if (warp == 0) {
                    float v0 = sh_sc[lane], v1 = sh_sc[lane + 32];
                    float v2 = sh_sc[lane + 64], v3 = sh_sc[lane + 96];
                    float m = fmaxf(fmaxf(v0, v1), fmaxf(v2, v3));
                    #pragma unroll
                    for (int o = 16; o; o >>= 1)
                        m = fmaxf(m, __shfl_xor_sync(0xffffffffu, m, o));
                    float e0 = __expf(v0 - m), e1 = __expf(v1 - m);
                    float e2 = __expf(v2 - m), e3 = __expf(v3 - m);
                    float sum = e0 + e1 + e2 + e3;
                    #pragma unroll
                    for (int o = 16; o; o >>= 1)
                        sum += __shfl_xor_sync(0xffffffffu, sum, o);
                    float inv = __fdividef(1.f, sum);
                    sh_sc[lane] = e0 * inv;        sh_sc[lane + 32] = e1 * inv;
                    sh_sc[lane + 64] = e2 * inv;   sh_sc[lane + 96] = e3 * inv;
                }
                __syncthreads();

                // ctx
                for (int e = tid; e < E; e += 256) {
                    float acc = 0.f;
                    const float* eb = &enc[((size_t)b * S) * E + e];
                    #pragma unroll 8
                    for (int s = 0; s < S; s++) acc += sh_sc[s] * eb[(size_t)s * E];
                    g_xh[b * KC + e] = acc;
                    g_hcatall[(size_t)(t * B + b) * KX + H + e] = acc;
                }
            }
        }
        if (t == T) return;
        grid_barrier();

        // ---------------- Phase B: gates MMA (all 128 blocks) --------------
        {
            unsigned* Ah = smem_u;
            unsigned* Al = Ah + 64 * MSTR;
            unsigned* Bh = Al + 64 * MSTR;
            unsigned* Bl = Bh + 128 * MSTR;
            int w2 = warp;
            int wm = w2 >> 2, wn = w2 & 3;
            int qr = lane >> 2, qc = lane & 3;
            int kc = blockIdx.x >> 4;
            int n0 = (blockIdx.x & 15) * 128;
            int kbase = kc * KCHUNK;

            int ar = tid >> 2, ac = (tid & 3) * 4;
            const float* Ag = g_xh + ar * KC + kbase + ac;
            int br = tid >> 1, bc = (tid & 1) * 8;
            const unsigned* Bhg = g_Wf_hi + (size_t)(n0 + br) * KC + kbase + bc;
            const unsigned* Blg = g_Wf_lo + (size_t)(n0 + br) * KC + kbase + bc;

            float acc[2][4][4] = {};
            #pragma unroll
            for (int kt = 0; kt < KCHUNK / 16; kt++) {
                int koff = kt * 16;
                float4 av = *(const float4*)(Ag + koff);
                uint4 bh0 = *(const uint4*)(Bhg + koff);
                uint4 bh1 = *(const uint4*)(Bhg + koff + 4);
                uint4 bl0 = *(const uint4*)(Blg + koff);
                uint4 bl1 = *(const uint4*)(Blg + koff + 4);
                __syncthreads();
                {
                    float a[4] = {av.x, av.y, av.z, av.w};
                    #pragma unroll
                    for (int i = 0; i < 4; i++) {
                        unsigned hi = f2tf32(a[i]);
                        Ah[ar * MSTR + ac + i] = hi;
                        Al[ar * MSTR + ac + i] = f2tf32(a[i] - __uint_as_float(hi));
                    }
                    unsigned* bp = &Bh[br * MSTR + bc];
                    bp[0] = bh0.x; bp[1] = bh0.y; bp[2] = bh0.z; bp[3] = bh0.w;
                    bp[4] = bh1.x; bp[5] = bh1.y; bp[6] = bh1.z; bp[7] = bh1.w;
                    unsigned* lp = &Bl[br * MSTR + bc];
                    lp[0] = bl0.x; lp[1] = bl0.y; lp[2] = bl0.z; lp[3] = bl0.w;
                    lp[4] = bl1.x; lp[5] = bl1.y; lp[6] = bl1.z; lp[7] = bl1.w;
                }
                __syncthreads();

                #pragma unroll
                for (int ks = 0; ks < 16; ks += 8) {
                    unsigned ah[2][4], al2[2][4], bhf[4][2], blf[4][2];
                    #pragma unroll
                    for (int mt = 0; mt < 2; mt++) {
                        int r = wm * 32 + mt * 16 + qr;
                        int c = ks + qc;
                        ah[mt][0] = Ah[r * MSTR + c];
                        ah[mt][1] = Ah[(r + 8) * MSTR + c];
                        ah[mt][2] = Ah[r * MSTR + c + 4];
                        ah[mt][3] = Ah[(r + 8) * MSTR + c + 4];
                        al2[mt][0] = Al[r * MSTR + c];
                        al2[mt][1] = Al[(r + 8) * MSTR + c];
                        al2[mt][2] = Al[r * MSTR + c + 4];
                        al2[mt][3] = Al[(r + 8) * MSTR + c + 4];
                    }
                    #pragma unroll
                    for (int nt = 0; nt < 4; nt++) {
                        int n = wn * 32 + nt * 8 + qr;
                        int c = ks + qc;
                        bhf[nt][0] = Bh[n * MSTR + c];
                        bhf[nt][1] = Bh[n * MSTR + c + 4];
                        blf[nt][0] = Bl[n * MSTR + c];
                        blf[nt][1] = Bl[n * MSTR + c + 4];
                    }
                    #pragma unroll
                    for (int mt = 0; mt < 2; mt++)
                        #pragma unroll
                        for (int nt = 0; nt < 4; nt++) {
                            mma_tf32(acc[mt][nt], ah[mt], bhf[nt]);
                            mma_tf32(acc[mt][nt], ah[mt], blf[nt]);
                            mma_tf32(acc[mt][nt], al2[mt], bhf[nt]);
                        }
                }
            }

            float* Cp = g_gpart + (size_t)kc * B * G4;
            #pragma unroll
            for (int mt = 0; mt < 2; mt++)
                #pragma unroll
                for (int nt = 0; nt < 4; nt++) {
                    int col = n0 + wn * 32 + nt * 8 + qc * 2;
                    #pragma unroll
                    for (int half = 0; half < 2; half++) {
                        int row = wm * 32 + mt * 16 + qr + half * 8;
                        float2 v = {acc[mt][nt][half * 2 + 0],
                                    acc[mt][nt][half * 2 + 1]};
                        *(float2*)&Cp[(size_t)row * G4 + col] = v;
                    }
                }
        }
        grid_barrier();
    }
}

// -------------------- TF32 tensor-core output GEMM (OBK=32) ----------------
#define OBK 32
#define SSTR 36
__global__ __launch_bounds__(256, 2)
void k_out_mma(const float* __restrict__ Bw, const float* __restrict__ bias,
               float* __restrict__ out) {
    __shared__ unsigned As[128 * SSTR];
    __shared__ unsigned Bs[128 * SSTR];
    int tid = threadIdx.x;
    int lane = tid & 31, w = tid >> 5;
    int wm = w >> 2, wn = w & 3;
    int m0 = blockIdx.y * 128, n0 = blockIdx.x * 128;

    int lrow = tid >> 1;
    int lcol = (tid & 1) * 16;
    const float* Ag = &g_hcatall[(size_t)(m0 + lrow) * KX + lcol];
    const float* Bg = Bw + (size_t)(n0 + lrow) * KX + lcol;

    float acc[4][4][4] = {};
    int qr = lane >> 2, qc = lane & 3;

    for (int k0 = 0; k0 < KX; k0 += OBK) {
        float4 a0 = *(const float4*)(Ag + k0);
        float4 a1 = *(const float4*)(Ag + k0 + 4);
        float4 a2 = *(const float4*)(Ag + k0 + 8);
        float4 a3 = *(const float4*)(Ag + k0 + 12);
        float4 b0 = *(const float4*)(Bg + k0);
        float4 b1 = *(const float4*)(Bg + k0 + 4);
        float4 b2 = *(const float4*)(Bg + k0 + 8);
        float4 b3 = *(const float4*)(Bg + k0 + 12);
        __syncthreads();
        {
            unsigned* ap = &As[lrow * SSTR + lcol];
            ap[0]  = f2tf32(a0.x); ap[1]  = f2tf32(a0.y);
            ap[2]  = f2tf32(a0.z); ap[3]  = f2tf32(a0.w);
            ap[4]  = f2tf32(a1.x); ap[5]  = f2tf32(a1.y);
            ap[6]  = f2tf32(a1.z); ap[7]  = f2tf32(a1.w);
            ap[8]  = f2tf32(a2.x); ap[9]  = f2tf32(a2.y);
            ap[10] = f2tf32(a2.z); ap[11] = f2tf32(a2.w);
            ap[12] = f2tf32(a3.x); ap[13] = f2tf32(a3.y);
            ap[14] = f2tf32(a3.z); ap[15] = f2tf32(a3.w);
            unsigned* bp = &Bs[lrow * SSTR + lcol];
            bp[0]  = f2tf32(b0.x); bp[1]  = f2tf32(b0.y);
            bp[2]  = f2tf32(b0.z); bp[3]  = f2tf32(b0.w);
            bp[4]  = f2tf32(b1.x); bp[5]  = f2tf32(b1.y);
            bp[6]  = f2tf32(b1.z); bp[7]  = f2tf32(b1.w);
            bp[8]  = f2tf32(b2.x); bp[9]  = f2tf32(b2.y);
            bp[10] = f2tf32(b2.z); bp[11] = f2tf32(b2.w);
            bp[12] = f2tf32(b3.x); bp[13] = f2tf32(b3.y);
            bp[14] = f2tf32(b3.z); bp[15] = f2tf32(b3.w);
        }
        __syncthreads();

        #pragma unroll
        for (int ks = 0; ks < OBK; ks += 8) {
            unsigned afr[4][4], bfr[4][2];
            #pragma unroll
            for (int mt = 0; mt < 4; mt++) {
                int r = wm * 64 + mt * 16 + qr;
                int c = ks + qc;
                afr[mt][0] = As[r * SSTR + c];
                afr[mt][1] = As[(r + 8) * SSTR + c];
                afr[mt][2] = As[r * SSTR + c + 4];
                afr[mt][3] = As[(r + 8) * SSTR + c + 4];
            }
            #pragma unroll
            for (int nt = 0; nt < 4; nt++) {
                int n = wn * 32 + nt * 8 + qr;
                int c = ks + qc;
                bfr[nt][0] = Bs[n * SSTR + c];
                bfr[nt][1] = Bs[n * SSTR + c + 4];
            }
            #pragma unroll
            for (int mt = 0; mt < 4; mt++)
                #pragma unroll
                for (int nt = 0; nt < 4; nt++)
                    mma_tf32(acc[mt][nt], afr[mt], bfr[nt]);
        }
    }

    #pragma unroll
    for (int mt = 0; mt < 4; mt++) {
        #pragma unroll
        for (int nt = 0; nt < 4; nt++) {
            int ncol = n0 + wn * 32 + nt * 8 + qc * 2;
            float bz0 = bias[ncol], bz1 = bias[ncol + 1];
            #pragma unroll
            for (int half = 0; half < 2; half++) {
                int r = m0 + wm * 64 + mt * 16 + qr + half * 8;
                int bidx = r & (B - 1);
                int tt = r >> 6;
                float* o = out + (size_t)bidx * T * V + (size_t)tt * V + ncol;
                float2 v = {acc[mt][nt][half * 2 + 0] + bz0,
                            acc[mt][nt][half * 2 + 1] + bz1};
                *(float2*)o = v;
            }
        }
    }
}

// -------------------- launch ------------------------------------------------
extern "C" void kernel_launch(void* const* d_in, const int* in_sizes, int n_in,
                              void* d_out, int out_size) {
    const float* enc   = (const float*)d_in[0];
    const int*   tgt   = (const int*)  d_in[1];
    const float* emb   = (const float*)d_in[2];
    const float* W_enc = (const float*)d_in[3];
    const float* W_dec = (const float*)d_in[4];
    const float* b_att = (const float*)d_in[5];
    const float* v_att = (const float*)d_in[6];
    const float* W_ih  = (const float*)d_in[7];
    const float* W_hh  = (const float*)d_in[8];
    const float* b_ih  = (const float*)d_in[9];
    const float* b_hh  = (const float*)d_in[10];
    const float* W_out = (const float*)d_in[11];
    const float* b_out = (const float*)d_in[12];
    float* out = (float*)d_out;

    float *p_encproj, *p_xe, *p_embpart;
    unsigned *p_WencT_hi, *p_WencT_lo, *p_We_hi, *p_We_lo;
    cudaGetSymbolAddress((void**)&p_encproj,  g_encproj);
    cudaGetSymbolAddress((void**)&p_xe,       g_xe);
    cudaGetSymbolAddress((void**)&p_embpart,  g_embpart);
    cudaGetSymbolAddress((void**)&p_WencT_hi, g_WencT_hi);
    cudaGetSymbolAddress((void**)&p_WencT_lo, g_WencT_lo);
    cudaGetSymbolAddress((void**)&p_We_hi,    g_We_hi);
    cudaGetSymbolAddress((void**)&p_We_lo,    g_We_lo);

    k_prep<<<512, 256>>>(W_enc, W_ih, W_hh, b_ih, b_hh, tgt, emb);

    // enc_proj[B*S, A] = enc @ W_enc (split-tf32)
    {
        dim3 grid(A_DIM / 128, (B * S) / 64, 1);
        k_mma_split<<<grid, 256>>>(enc, E, p_WencT_hi, p_WencT_lo, E,
                                   p_encproj, A_DIM, 0, E);
    }
    // embpart[T*B, G4] = xe @ We^T (split-tf32), once for all steps
    {
        dim3 grid(G4 / 128, (T * B) / 64, 1);
        k_mma_split<<<grid, 256>>>(p_xe, H, p_We_hi, p_We_lo, H,
                                   p_embpart, G4, 0, H);
    }

    // whole decode loop in one persistent kernel
    k_loop<<<NB, 256>>>(enc, W_dec, b_att, v_att);

    // output projection for all timesteps
    {
        dim3 grid(V / 128, (T * B) / 128);
        k_out_mma<<<grid, 256>>>(W_out, b_out, out);
    }
}

// round 7
// speedup vs baseline: 4.5194x; 1.0184x over previous
#include <cuda_runtime.h>
#include <math.h>

// Problem constants
#define B     64
#define S     128
#define E     512
#define H     512
#define A_DIM 256
#define V     8192
#define T     32
#define KX    1024   // H + E (out-proj input [h|ctx])
#define KC    1024   // per-step gates input [ctx|h]
#define G4    2048   // 4*H
#define KSPLIT 8
#define KCHUNK (KC / KSPLIT)   // 128
#define NB    128    // persistent grid size

// smem layout (words) for k_loop dynamic smem
#define WSTR  132                       // padded row stride (128 + 4)
#define OFF_BH 0
#define OFF_BL (128 * WSTR)             // 16896
#define OFF_AH (2 * 128 * WSTR)         // 33792
#define OFF_AL (OFF_AH + 64 * WSTR)     // 42240
#define LOOP_SMEM_WORDS (OFF_AL + 64 * WSTR)   // 50688 words = 202752 B

// -------------------- scratch (device globals) -----------------------------
__device__ float    g_encproj[B * S * A_DIM];
__device__ unsigned g_WencT_hi[A_DIM * E];
__device__ unsigned g_WencT_lo[A_DIM * E];
__device__ unsigned g_Wf_hi[G4 * KC];        // [ctx | h] weights
__device__ unsigned g_Wf_lo[G4 * KC];
__device__ unsigned g_We_hi[G4 * H];         // emb weights
__device__ unsigned g_We_lo[G4 * H];
__device__ float    g_bf[G4];
__device__ float    g_xh[B * KC];            // [ctx | h_prev]
__device__ float    g_xe[T * B * H];         // gathered embeddings
__device__ float    g_embpart[T * B * G4];   // emb @ We^T, all steps
__device__ float    g_hcatall[T * B * KX];   // [h_t | ctx_t] all steps
__device__ float    g_c[B * H];
__device__ float    g_gpart[KSPLIT * B * G4];
__device__ unsigned g_bar_count = 0;
__device__ unsigned g_bar_phase = 0;

// -------------------- helpers ----------------------------------------------
__device__ __forceinline__ unsigned f2tf32(float x) {
    unsigned r;
    asm("cvt.rna.tf32.f32 %0, %1;" : "=r"(r) : "f"(x));
    return r;
}
__device__ __forceinline__ float tanh_fast(float x) {
    float y;
    asm("tanh.approx.f32 %0, %1;" : "=f"(y) : "f"(x));
    return y;
}
__device__ __forceinline__ float sigmoid_fast(float x) {
    return __fdividef(1.f, 1.f + __expf(-x));
}
__device__ __forceinline__ void mma_tf32(float* d, const unsigned* a, const unsigned* b) {
    asm("mma.sync.aligned.m16n8k8.row.col.f32.tf32.tf32.f32 "
        "{%0,%1,%2,%3}, {%4,%5,%6,%7}, {%8,%9}, {%0,%1,%2,%3};"
        : "+f"(d[0]), "+f"(d[1]), "+f"(d[2]), "+f"(d[3])
        : "r"(a[0]), "r"(a[1]), "r"(a[2]), "r"(a[3]), "r"(b[0]), "r"(b[1]));
}

__device__ __forceinline__ void grid_barrier() {
    __syncthreads();
    if (threadIdx.x == 0) {
        __threadfence();
        unsigned gen = *((volatile unsigned*)&g_bar_phase);
        if (atomicAdd(&g_bar_count, 1u) == NB - 1) {
            *((volatile unsigned*)&g_bar_count) = 0;
            __threadfence();
            *((volatile unsigned*)&g_bar_phase) = gen + 1;
        } else {
            while (*((volatile unsigned*)&g_bar_phase) == gen) {}
        }
        __threadfence();
    }
    __syncthreads();
}

// -------------------- setup (incl. embedding gather) -----------------------
__global__ void k_prep(const float* __restrict__ W_enc,
                       const float* __restrict__ W_ih,
                       const float* __restrict__ W_hh,
                       const float* __restrict__ b_ih,
                       const float* __restrict__ b_hh,
                       const int* __restrict__ tgt,
                       const float* __restrict__ emb) {
    int stride = gridDim.x * blockDim.x;
    int tid0 = blockIdx.x * blockDim.x + threadIdx.x;
    for (int i = tid0; i < A_DIM * E; i += stride) {
        int a = i / E, e = i % E;
        float v = W_enc[e * A_DIM + a];
        unsigned hi = f2tf32(v);
        g_WencT_hi[i] = hi;
        g_WencT_lo[i] = f2tf32(v - __uint_as_float(hi));
    }
    for (int i = tid0; i < G4 * KC; i += stride) {
        int j = i / KC, k = i % KC;
        float v = (k < H) ? W_ih[j * KX + H + k] : W_hh[j * H + (k - H)];
        unsigned hi = f2tf32(v);
        g_Wf_hi[i] = hi;
        g_Wf_lo[i] = f2tf32(v - __uint_as_float(hi));
    }
    for (int i = tid0; i < G4 * H; i += stride) {
        int j = i / H, k = i % H;
        float v = W_ih[j * KX + k];
        unsigned hi = f2tf32(v);
        g_We_hi[i] = hi;
        g_We_lo[i] = f2tf32(v - __uint_as_float(hi));
    }
    for (int i = tid0; i < G4; i += stride) g_bf[i] = b_ih[i] + b_hh[i];
    for (int i = tid0; i < B * H; i += stride) {
        g_c[i] = 0.0f;
        int b = i / H, j = i % H;
        g_xh[b * KC + H + j] = 0.0f;   // h0 = 0
    }
    for (int i = tid0; i < T * B * H; i += stride) {
        int r = i >> 9, k = i & 511;
        int t = r >> 6, b = r & 63;
        int tok = (t == 0) ? 0 : tgt[b * T + t - 1];
        g_xe[i] = emb[(size_t)tok * H + k];
    }
}

// -------------------- split-TF32 tensor-core GEMM (standalone) -------------
#define MSTR 20
__global__ __launch_bounds__(256, 2)
void k_mma_split(const float* __restrict__ A, int lda,
                 const unsigned* __restrict__ Bhi,
                 const unsigned* __restrict__ Blo, int ldb,
                 float* __restrict__ C, int ldc, size_t czstride,
                 int kchunk) {
    __shared__ unsigned Ah[64 * MSTR], Al[64 * MSTR];
    __shared__ unsigned Bh[128 * MSTR], Bl[128 * MSTR];
    int tid = threadIdx.x;
    int lane = tid & 31, w = tid >> 5;
    int wm = w >> 2, wn = w & 3;
    int qr = lane >> 2, qc = lane & 3;
    int m0 = blockIdx.y * 64, n0 = blockIdx.x * 128;
    int kbase = blockIdx.z * kchunk;

    int ar = tid >> 2, ac = (tid & 3) * 4;
    const float* Ag = A + (size_t)(m0 + ar) * lda + kbase + ac;
    int br = tid >> 1, bc = (tid & 1) * 8;
    const unsigned* Bhg = Bhi + (size_t)(n0 + br) * ldb + kbase + bc;
    const unsigned* Blg = Blo + (size_t)(n0 + br) * ldb + kbase + bc;

    float acc[2][4][4] = {};
    int nk = kchunk >> 4;
    for (int kt = 0; kt < nk; kt++) {
        int koff = kt * 16;
        float4 av = *(const float4*)(Ag + koff);
        uint4 bh0 = *(const uint4*)(Bhg + koff);
        uint4 bh1 = *(const uint4*)(Bhg + koff + 4);
        uint4 bl0 = *(const uint4*)(Blg + koff);
        uint4 bl1 = *(const uint4*)(Blg + koff + 4);
        __syncthreads();
        {
            float a[4] = {av.x, av.y, av.z, av.w};
            #pragma unroll
            for (int i = 0; i < 4; i++) {
                unsigned hi = f2tf32(a[i]);
                Ah[ar * MSTR + ac + i] = hi;
                Al[ar * MSTR + ac + i] = f2tf32(a[i] - __uint_as_float(hi));
            }
            unsigned* bp = &Bh[br * MSTR + bc];
            bp[0] = bh0.x; bp[1] = bh0.y; bp[2] = bh0.z; bp[3] = bh0.w;
            bp[4] = bh1.x; bp[5] = bh1.y; bp[6] = bh1.z; bp[7] = bh1.w;
            unsigned* lp = &Bl[br * MSTR + bc];
            lp[0] = bl0.x; lp[1] = bl0.y; lp[2] = bl0.z; lp[3] = bl0.w;
            lp[4] = bl1.x; lp[5] = bl1.y; lp[6] = bl1.z; lp[7] = bl1.w;
        }
        __syncthreads();

        #pragma unroll
        for (int ks = 0; ks < 16; ks += 8) {
            unsigned ah[2][4], al[2][4], bhf[4][2], blf[4][2];
            #pragma unroll
            for (int mt = 0; mt < 2; mt++) {
                int r = wm * 32 + mt * 16 + qr;
                int c = ks + qc;
                ah[mt][0] = Ah[r * MSTR + c];
                ah[mt][1] = Ah[(r + 8) * MSTR + c];
                ah[mt][2] = Ah[r * MSTR + c + 4];
                ah[mt][3] = Ah[(r + 8) * MSTR + c + 4];
                al[mt][0] = Al[r * MSTR + c];
                al[mt][1] = Al[(r + 8) * MSTR + c];
                al[mt][2] = Al[r * MSTR + c + 4];
                al[mt][3] = Al[(r + 8) * MSTR + c + 4];
            }
            #pragma unroll
            for (int nt = 0; nt < 4; nt++) {
                int n = wn * 32 + nt * 8 + qr;
                int c = ks + qc;
                bhf[nt][0] = Bh[n * MSTR + c];
                bhf[nt][1] = Bh[n * MSTR + c + 4];
                blf[nt][0] = Bl[n * MSTR + c];
                blf[nt][1] = Bl[n * MSTR + c + 4];
            }
            #pragma unroll
            for (int mt = 0; mt < 2; mt++)
                #pragma unroll
                for (int nt = 0; nt < 4; nt++) {
                    mma_tf32(acc[mt][nt], ah[mt], bhf[nt]);
                    mma_tf32(acc[mt][nt], ah[mt], blf[nt]);
                    mma_tf32(acc[mt][nt], al[mt], bhf[nt]);
                }
        }
    }

    float* Cp = C + (size_t)blockIdx.z * czstride;
    #pragma unroll
    for (int mt = 0; mt < 2; mt++)
        #pragma unroll
        for (int nt = 0; nt < 4; nt++) {
            int col = n0 + wn * 32 + nt * 8 + qc * 2;
            #pragma unroll
            for (int half = 0; half < 2; half++) {
                int row = m0 + wm * 32 + mt * 16 + qr + half * 8;
                float2 v = {acc[mt][nt][half * 2 + 0],
                            acc[mt][nt][half * 2 + 1]};
                *(float2*)&Cp[(size_t)row * ldc + col] = v;
            }
        }
}

// -------------------- persistent step loop (weight-stationary) --------------
// grid = 128 blocks x 256 threads, 1 block/SM (198 KB dynamic smem each).
// Each block pins its 128x128 hi/lo gates-weight tile in smem for all steps.
__global__ __launch_bounds__(256, 1)
void k_loop(const float* __restrict__ enc, const float* __restrict__ W_dec,
            const float* __restrict__ b_att, const float* __restrict__ v_att) {
    extern __shared__ __align__(16) unsigned dyn[];
    int tid = threadIdx.x;
    int lane = tid & 31, warp = tid >> 5;
    int kc = blockIdx.x >> 4;
    int n0 = (blockIdx.x & 15) * 128;
    int kbase = kc * KCHUNK;

    unsigned* Bh = dyn + OFF_BH;
    unsigned* Bl = dyn + OFF_BL;
    unsigned* Ah = dyn + OFF_AH;
    unsigned* Al = dyn + OFF_AL;

    // one-time: pin this block's weight tile in smem
    {
        int r = tid >> 1;                 // 0..127
        int cb = (tid & 1) * 64;          // 0 or 64
        const unsigned* hg = g_Wf_hi + (size_t)(n0 + r) * KC + kbase + cb;
        const unsigned* lg = g_Wf_lo + (size_t)(n0 + r) * KC + kbase + cb;
        #pragma unroll
        for (int j = 0; j < 16; j++) {
            uint4 hv = *(const uint4*)(hg + j * 4);
            uint4 lv = *(const uint4*)(lg + j * 4);
            unsigned* hp = &Bh[r * WSTR + cb + j * 4];
            unsigned* lp = &Bl[r * WSTR + cb + j * 4];
            hp[0] = hv.x; hp[1] = hv.y; hp[2] = hv.z; hp[3] = hv.w;
            lp[0] = lv.x; lp[1] = lv.y; lp[2] = lv.z; lp[3] = lv.w;
        }
    }
    __syncthreads();

    for (int t = 0; t <= T; t++) {
        // ---------------- Phase A (blocks 0..63) ----------------
        if (blockIdx.x < B) {
            int b = blockIdx.x;
            float* sh_h  = (float*)(dyn + OFF_AH);  // aliases A staging
            float* sh_dp = sh_h + 512;
            float* sh_v  = sh_dp + 256;
            float* sh_sc = sh_v + 256;

            if (t > 0) {
                const float* ep = &g_embpart[(size_t)((t - 1) * B + b) * G4];
                #pragma unroll
                for (int jj = 0; jj < 2; jj++) {
                    int j = tid + jj * 256;
                    float gi = g_bf[j] + ep[j];
                    float gf = g_bf[j + H] + ep[j + H];
                    float gg = g_bf[j + 2 * H] + ep[j + 2 * H];
                    float go = g_bf[j + 3 * H] + ep[j + 3 * H];
                    #pragma unroll
                    for (int p = 0; p < KSPLIT; p++) {
                        const float* gp = &g_gpart[(size_t)(p * B + b) * G4];
                        gi += gp[j];         gf += gp[j + H];
                        gg += gp[j + 2 * H]; go += gp[j + 3 * H];
                    }
                    float c = g_c[b * H + j];
                    float cn = sigmoid_fast(gf) * c + sigmoid_fast(gi) * tanh_fast(gg);
                    float hn = sigmoid_fast(go) * tanh_fast(cn);
                    g_c[b * H + j] = cn;
                    sh_h[j] = hn;
                    g_xh[b * KC + H + j] = hn;
                    g_hcatall[(size_t)((t - 1) * B + b) * KX + j] = hn;
                }
            } else {
                sh_h[tid] = 0.f;
                sh_h[tid + 256] = 0.f;
            }
            if (t < T) {
                sh_v[tid] = v_att[tid];
                __syncthreads();

                // dp[a] = b_att[a] + h . W_dec[:,a]
                {
                    float acc = b_att[tid];
                    #pragma unroll 8
                    for (int e = 0; e < H; e++) acc += sh_h[e] * W_dec[e * A_DIM + tid];
                    sh_dp[tid] = acc;
                }
                __syncthreads();

                // scores
                for (int s = warp; s < S; s += 8) {
                    const float* ep2 = &g_encproj[((size_t)b * S + s) * A_DIM];
                    float acc = 0.f;
                    #pragma unroll
                    for (int a = lane; a < A_DIM; a += 32)
                        acc += tanh_fast(ep2[a] + sh_dp[a]) * sh_v[a];
                    #pragma unroll
                    for (int o = 16; o; o >>= 1)
                        acc += __shfl_xor_sync(0xffffffffu, acc, o);
                    if (lane == 0) sh_sc[s] = acc;
                }
                __syncthreads();

                // softmax
                if (warp == 0) {
                    float v0 = sh_sc[lane], v1 = sh_sc[lane + 32];
                    float v2 = sh_sc[lane + 64], v3 = sh_sc[lane + 96];
                    float m = fmaxf(fmaxf(v0, v1), fmaxf(v2, v3));
                    #pragma unroll
                    for (int o = 16; o; o >>= 1)
                        m = fmaxf(m, __shfl_xor_sync(0xffffffffu, m, o));
                    float e0 = __expf(v0 - m), e1 = __expf(v1 - m);
                    float e2 = __expf(v2 - m), e3 = __expf(v3 - m);
                    float sum = e0 + e1 + e2 + e3;
                    #pragma unroll
                    for (int o = 16; o; o >>= 1)
                        sum += __shfl_xor_sync(0xffffffffu, sum, o);
                    float inv = __fdividef(1.f, sum);
                    sh_sc[lane] = e0 * inv;        sh_sc[lane + 32] = e1 * inv;
                    sh_sc[lane + 64] = e2 * inv;   sh_sc[lane + 96] = e3 * inv;
                }
                __syncthreads();

                // ctx
                for (int e = tid; e < E; e += 256) {
                    float acc = 0.f;
                    const float* eb = &enc[((size_t)b * S) * E + e];
                    #pragma unroll 8
                    for (int s = 0; s < S; s++) acc += sh_sc[s] * eb[(size_t)s * E];
                    g_xh[b * KC + e] = acc;
                    g_hcatall[(size_t)(t * B + b) * KX + H + e] = acc;
                }
            }
        }
        if (t == T) return;
        grid_barrier();

        // ---------------- Phase B: gates MMA (weight-stationary) -----------
        {
            int wm = warp >> 2, wn = warp & 3;
            int qr = lane >> 2, qc = lane & 3;

            // stage A tile (64 x 128) -> hi/lo smem
            {
                int ar = tid >> 2;               // 0..63
                int acb = (tid & 3) * 32;        // 0,32,64,96
                const float* Ag = g_xh + ar * KC + kbase + acb;
                #pragma unroll
                for (int j = 0; j < 8; j++) {
                    float4 v = *(const float4*)(Ag + j * 4);
                    float a[4] = {v.x, v.y, v.z, v.w};
                    #pragma unroll
                    for (int i = 0; i < 4; i++) {
                        unsigned hi = f2tf32(a[i]);
                        Ah[ar * WSTR + acb + j * 4 + i] = hi;
                        Al[ar * WSTR + acb + j * 4 + i] =
                            f2tf32(a[i] - __uint_as_float(hi));
                    }
                }
            }
            __syncthreads();

            float acc[2][4][4] = {};
            #pragma unroll
            for (int ks = 0; ks < KCHUNK; ks += 8) {
                unsigned ah[2][4], al2[2][4], bhf[4][2], blf[4][2];
                #pragma unroll
                for (int mt = 0; mt < 2; mt++) {
                    int r = wm * 32 + mt * 16 + qr;
                    int c = ks + qc;
                    ah[mt][0] = Ah[r * WSTR + c];
                    ah[mt][1] = Ah[(r + 8) * WSTR + c];
                    ah[mt][2] = Ah[r * WSTR + c + 4];
                    ah[mt][3] = Ah[(r + 8) * WSTR + c + 4];
                    al2[mt][0] = Al[r * WSTR + c];
                    al2[mt][1] = Al[(r + 8) * WSTR + c];
                    al2[mt][2] = Al[r * WSTR + c + 4];
                    al2[mt][3] = Al[(r + 8) * WSTR + c + 4];
                }
                #pragma unroll
                for (int nt = 0; nt < 4; nt++) {
                    int n = wn * 32 + nt * 8 + qr;
                    int c = ks + qc;
                    bhf[nt][0] = Bh[n * WSTR + c];
                    bhf[nt][1] = Bh[n * WSTR + c + 4];
                    blf[nt][0] = Bl[n * WSTR + c];
                    blf[nt][1] = Bl[n * WSTR + c + 4];
                }
                #pragma unroll
                for (int mt = 0; mt < 2; mt++)
                    #pragma unroll
                    for (int nt = 0; nt < 4; nt++) {
                        mma_tf32(acc[mt][nt], ah[mt], bhf[nt]);
                        mma_tf32(acc[mt][nt], ah[mt], blf[nt]);
                        mma_tf32(acc[mt][nt], al2[mt], bhf[nt]);
                    }
            }

            float* Cp = g_gpart + (size_t)kc * B * G4;
            #pragma unroll
            for (int mt = 0; mt < 2; mt++)
                #pragma unroll
                for (int nt = 0; nt < 4; nt++) {
                    int col = n0 + wn * 32 + nt * 8 + qc * 2;
                    #pragma unroll
                    for (int half = 0; half < 2; half++) {
                        int row = wm * 32 + mt * 16 + qr + half * 8;
                        float2 v = {acc[mt][nt][half * 2 + 0],
                                    acc[mt][nt][half * 2 + 1]};
                        *(float2*)&Cp[(size_t)row * G4 + col] = v;
                    }
                }
        }
        grid_barrier();
    }
}

// -------------------- TF32 tensor-core output GEMM (OBK=32) ----------------
#define OBK 32
#define SSTR 36
__global__ __launch_bounds__(256, 2)
void k_out_mma(const float* __restrict__ Bw, const float* __restrict__ bias,
               float* __restrict__ out) {
    __shared__ unsigned As[128 * SSTR];
    __shared__ unsigned Bs[128 * SSTR];
    int tid = threadIdx.x;
    int lane = tid & 31, w = tid >> 5;
    int wm = w >> 2, wn = w & 3;
    int m0 = blockIdx.y * 128, n0 = blockIdx.x * 128;

    int lrow = tid >> 1;
    int lcol = (tid & 1) * 16;
    const float* Ag = &g_hcatall[(size_t)(m0 + lrow) * KX + lcol];
    const float* Bg = Bw + (size_t)(n0 + lrow) * KX + lcol;

    float acc[4][4][4] = {};
    int qr = lane >> 2, qc = lane & 3;

    for (int k0 = 0; k0 < KX; k0 += OBK) {
        float4 a0 = *(const float4*)(Ag + k0);
        float4 a1 = *(const float4*)(Ag + k0 + 4);
        float4 a2 = *(const float4*)(Ag + k0 + 8);
        float4 a3 = *(const float4*)(Ag + k0 + 12);
        float4 b0 = *(const float4*)(Bg + k0);
        float4 b1 = *(const float4*)(Bg + k0 + 4);
        float4 b2 = *(const float4*)(Bg + k0 + 8);
        float4 b3 = *(const float4*)(Bg + k0 + 12);
        __syncthreads();
        {
            unsigned* ap = &As[lrow * SSTR + lcol];
            ap[0]  = f2tf32(a0.x); ap[1]  = f2tf32(a0.y);
            ap[2]  = f2tf32(a0.z); ap[3]  = f2tf32(a0.w);
            ap[4]  = f2tf32(a1.x); ap[5]  = f2tf32(a1.y);
            ap[6]  = f2tf32(a1.z); ap[7]  = f2tf32(a1.w);
            ap[8]  = f2tf32(a2.x); ap[9]  = f2tf32(a2.y);
            ap[10] = f2tf32(a2.z); ap[11] = f2tf32(a2.w);
            ap[12] = f2tf32(a3.x); ap[13] = f2tf32(a3.y);
            ap[14] = f2tf32(a3.z); ap[15] = f2tf32(a3.w);
            unsigned* bp = &Bs[lrow * SSTR + lcol];
            bp[0]  = f2tf32(b0.x); bp[1]  = f2tf32(b0.y);
            bp[2]  = f2tf32(b0.z); bp[3]  = f2tf32(b0.w);
            bp[4]  = f2tf32(b1.x); bp[5]  = f2tf32(b1.y);
            bp[6]  = f2tf32(b1.z); bp[7]  = f2tf32(b1.w);
            bp[8]  = f2tf32(b2.x); bp[9]  = f2tf32(b2.y);
            bp[10] = f2tf32(b2.z); bp[11] = f2tf32(b2.w);
            bp[12] = f2tf32(b3.x); bp[13] = f2tf32(b3.y);
            bp[14] = f2tf32(b3.z); bp[15] = f2tf32(b3.w);
        }
        __syncthreads();

        #pragma unroll
        for (int ks = 0; ks < OBK; ks += 8) {
            unsigned afr[4][4], bfr[4][2];
            #pragma unroll
            for (int mt = 0; mt < 4; mt++) {
                int r = wm * 64 + mt * 16 + qr;
                int c = ks + qc;
                afr[mt][0] = As[r * SSTR + c];
                afr[mt][1] = As[(r + 8) * SSTR + c];
                afr[mt][2] = As[r * SSTR + c + 4];
                afr[mt][3] = As[(r + 8) * SSTR + c + 4];
            }
            #pragma unroll
            for (int nt = 0; nt < 4; nt++) {
                int n = wn * 32 + nt * 8 + qr;
                int c = ks + qc;
                bfr[nt][0] = Bs[n * SSTR + c];
                bfr[nt][1] = Bs[n * SSTR + c + 4];
            }
            #pragma unroll
            for (int mt = 0; mt < 4; mt++)
                #pragma unroll
                for (int nt = 0; nt < 4; nt++)
                    mma_tf32(acc[mt][nt], afr[mt], bfr[nt]);
        }
    }

    #pragma unroll
    for (int mt = 0; mt < 4; mt++) {
        #pragma unroll
        for (int nt = 0; nt < 4; nt++) {
            int ncol = n0 + wn * 32 + nt * 8 + qc * 2;
            float bz0 = bias[ncol], bz1 = bias[ncol + 1];
            #pragma unroll
            for (int half = 0; half < 2; half++) {
                int r = m0 + wm * 64 + mt * 16 + qr + half * 8;
                int bidx = r & (B - 1);
                int tt = r >> 6;
                float* o = out + (size_t)bidx * T * V + (size_t)tt * V + ncol;
                float2 v = {acc[mt][nt][half * 2 + 0] + bz0,
                            acc[mt][nt][half * 2 + 1] + bz1};
                *(float2*)o = v;
            }
        }
    }
}

// -------------------- launch ------------------------------------------------
extern "C" void kernel_launch(void* const* d_in, const int* in_sizes, int n_in,
                              void* d_out, int out_size) {
    const float* enc   = (const float*)d_in[0];
    const int*   tgt   = (const int*)  d_in[1];
    const float* emb   = (const float*)d_in[2];
    const float* W_enc = (const float*)d_in[3];
    const float* W_dec = (const float*)d_in[4];
    const float* b_att = (const float*)d_in[5];
    const float* v_att = (const float*)d_in[6];
    const float* W_ih  = (const float*)d_in[7];
    const float* W_hh  = (const float*)d_in[8];
    const float* b_ih  = (const float*)d_in[9];
    const float* b_hh  = (const float*)d_in[10];
    const float* W_out = (const float*)d_in[11];
    const float* b_out = (const float*)d_in[12];
    float* out = (float*)d_out;

    float *p_encproj, *p_xe, *p_embpart;
    unsigned *p_WencT_hi, *p_WencT_lo, *p_We_hi, *p_We_lo;
    cudaGetSymbolAddress((void**)&p_encproj,  g_encproj);
    cudaGetSymbolAddress((void**)&p_xe,       g_xe);
    cudaGetSymbolAddress((void**)&p_embpart,  g_embpart);
    cudaGetSymbolAddress((void**)&p_WencT_hi, g_WencT_hi);
    cudaGetSymbolAddress((void**)&p_WencT_lo, g_WencT_lo);
    cudaGetSymbolAddress((void**)&p_We_hi,    g_We_hi);
    cudaGetSymbolAddress((void**)&p_We_lo,    g_We_lo);

    static bool attr_done = false;
    if (!attr_done) {
        cudaFuncSetAttribute(k_loop, cudaFuncAttributeMaxDynamicSharedMemorySize,
                             LOOP_SMEM_WORDS * 4);
        attr_done = true;
    }

    k_prep<<<512, 256>>>(W_enc, W_ih, W_hh, b_ih, b_hh, tgt, emb);

    // enc_proj[B*S, A] = enc @ W_enc (split-tf32)
    {
        dim3 grid(A_DIM / 128, (B * S) / 64, 1);
        k_mma_split<<<grid, 256>>>(enc, E, p_WencT_hi, p_WencT_lo, E,
                                   p_encproj, A_DIM, 0, E);
    }
    // embpart[T*B, G4] = xe @ We^T (split-tf32), once for all steps
    {
        dim3 grid(G4 / 128, (T * B) / 64, 1);
        k_mma_split<<<grid, 256>>>(p_xe, H, p_We_hi, p_We_lo, H,
                                   p_embpart, G4, 0, H);
    }

    // whole decode loop in one persistent, weight-stationary kernel
    k_loop<<<NB, 256, LOOP_SMEM_WORDS * 4>>>(enc, W_dec, b_att, v_att);

    // output projection for all timesteps
    {
        dim3 grid(V / 128, (T * B) / 128);
        k_out_mma<<<grid, 256>>>(W_out, b_out, out);
    }
}